// round 1
// baseline (speedup 1.0000x reference)
#include <cuda_runtime.h>
#include <math.h>

// Problem constants
#define BB 2
#define TT 2048
#define DD 1024
#define HH 16
#define DK 64

// Scratch (device globals: no allocations allowed)
__device__ float g_q[BB*HH*TT*DK];     // [B,H,T,DK]
__device__ float g_k[BB*HH*TT*DK];     // [B,H,T,DK]
__device__ float g_v[BB*HH*TT*DK];     // [B,H,T,DK]
__device__ float g_attn[(size_t)BB*TT*DD]; // [B,T,D]

// ---------------------------------------------------------------------------
// C = A @ W^T.  A: [M, 1024] row-major, W: [1024, 1024] row-major ([out,in]).
// perm==1: scatter C[m, e] to [B,H,T,DK] layout (for Q/K/V).
// perm==0: row-major C [M, 1024].
// Tiles: 64x64x16, 256 threads, 4x4 micro-tile per thread.
// ---------------------------------------------------------------------------
__global__ void proj_kernel(const float* __restrict__ A,
                            const float* __restrict__ W,
                            float* __restrict__ C,
                            int perm)
{
    __shared__ float As[64 * 20];
    __shared__ float Ws[64 * 20];

    const int t  = threadIdx.x;
    const int tx = t & 15;
    const int ty = t >> 4;
    const int m0 = blockIdx.y * 64;
    const int n0 = blockIdx.x * 64;

    const int lrow = t >> 2;          // 0..63
    const int lc4  = (t & 3) << 2;    // 0,4,8,12

    float acc[4][4] = {};

    for (int k0 = 0; k0 < 1024; k0 += 16) {
        float4 a4 = *(const float4*)(A + (size_t)(m0 + lrow) * 1024 + k0 + lc4);
        *(float4*)(As + lrow * 20 + lc4) = a4;
        float4 w4 = *(const float4*)(W + (size_t)(n0 + lrow) * 1024 + k0 + lc4);
        *(float4*)(Ws + lrow * 20 + lc4) = w4;
        __syncthreads();

        #pragma unroll
        for (int kk = 0; kk < 16; kk++) {
            float ra[4], rb[4];
            #pragma unroll
            for (int i = 0; i < 4; i++) ra[i] = As[(ty * 4 + i) * 20 + kk];
            #pragma unroll
            for (int j = 0; j < 4; j++) rb[j] = Ws[(tx * 4 + j) * 20 + kk];
            #pragma unroll
            for (int i = 0; i < 4; i++)
                #pragma unroll
                for (int j = 0; j < 4; j++)
                    acc[i][j] = fmaf(ra[i], rb[j], acc[i][j]);
        }
        __syncthreads();
    }

    #pragma unroll
    for (int i = 0; i < 4; i++) {
        const int m = m0 + ty * 4 + i;
        #pragma unroll
        for (int j = 0; j < 4; j++) {
            const int n = n0 + tx * 4 + j;
            if (perm) {
                const int b  = m >> 11;      // m / T
                const int tq = m & 2047;     // m % T
                const int h  = n >> 6;       // n / DK
                const int dk = n & 63;       // n % DK
                g_q[0]; // no-op keep symbol usage explicit
                C[(((size_t)(b * HH + h) * TT + tq) << 6) + dk] = acc[i][j];
            } else {
                C[(size_t)m * 1024 + n] = acc[i][j];
            }
        }
    }
}

// ---------------------------------------------------------------------------
// Fused attention: per CTA = one (b,h) and a 64-row Q tile, full key loop.
// Pass A: online softmax stats (max,sum). Pass B: recompute S, write
// normalized weights (single coalesced write), accumulate O = W @ V.
// 256 threads, 4x4 micro-tiles; dyn smem: Qs/KVs/Ws each [64][68].
// ---------------------------------------------------------------------------
#define SST 68  // smem row stride (floats), multiple of 4 for float4

extern __shared__ float sm_attn[];

__global__ void attn_kernel(float* __restrict__ wout)
{
    float* Qs = sm_attn;
    float* KV = sm_attn + 64 * SST;
    float* Ws = sm_attn + 2 * 64 * SST;

    const int bh = blockIdx.y;          // b*H + h
    const int q0 = blockIdx.x * 64;
    const float* Qg = g_q + (size_t)bh * TT * DK;
    const float* Kg = g_k + (size_t)bh * TT * DK;
    const float* Vg = g_v + (size_t)bh * TT * DK;

    const int t  = threadIdx.x;
    const int tx = t & 15;
    const int ty = t >> 4;

    // Load Q tile (pre-scaled by 1/sqrt(DK) = 0.125)
    #pragma unroll
    for (int r = 0; r < 4; r++) {
        const int idx = t + r * 256;          // float4 index 0..1023
        const int row = idx >> 4;
        const int c4  = (idx & 15) << 2;
        float4 v = *(const float4*)(Qg + (size_t)(q0 + row) * DK + c4);
        float* d = Qs + row * SST + c4;
        d[0] = v.x * 0.125f; d[1] = v.y * 0.125f;
        d[2] = v.z * 0.125f; d[3] = v.w * 0.125f;
    }
    __syncthreads();

    float m_[4], l_[4];
    #pragma unroll
    for (int i = 0; i < 4; i++) { m_[i] = -1e30f; l_[i] = 0.0f; }

    // ---------------- Pass A: stats ----------------
    for (int kt = 0; kt < TT / 64; kt++) {
        #pragma unroll
        for (int r = 0; r < 4; r++) {
            const int idx = t + r * 256;
            const int row = idx >> 4;
            const int c4  = (idx & 15) << 2;
            *(float4*)(KV + row * SST + c4) =
                *(const float4*)(Kg + (size_t)(kt * 64 + row) * DK + c4);
        }
        __syncthreads();

        float s[4][4] = {};
        #pragma unroll 8
        for (int kk = 0; kk < 64; kk++) {
            float ra[4], rb[4];
            #pragma unroll
            for (int i = 0; i < 4; i++) ra[i] = Qs[(ty * 4 + i) * SST + kk];
            #pragma unroll
            for (int j = 0; j < 4; j++) rb[j] = KV[(tx * 4 + j) * SST + kk];
            #pragma unroll
            for (int i = 0; i < 4; i++)
                #pragma unroll
                for (int j = 0; j < 4; j++)
                    s[i][j] = fmaf(ra[i], rb[j], s[i][j]);
        }

        #pragma unroll
        for (int i = 0; i < 4; i++) {
            float tm = fmaxf(fmaxf(s[i][0], s[i][1]), fmaxf(s[i][2], s[i][3]));
            #pragma unroll
            for (int off = 1; off < 16; off <<= 1)
                tm = fmaxf(tm, __shfl_xor_sync(0xffffffffu, tm, off));
            const float nm = fmaxf(m_[i], tm);
            float sum = __expf(s[i][0] - nm) + __expf(s[i][1] - nm)
                      + __expf(s[i][2] - nm) + __expf(s[i][3] - nm);
            #pragma unroll
            for (int off = 1; off < 16; off <<= 1)
                sum += __shfl_xor_sync(0xffffffffu, sum, off);
            l_[i] = l_[i] * __expf(m_[i] - nm) + sum;
            m_[i] = nm;
        }
        __syncthreads();
    }

    float inv[4];
    #pragma unroll
    for (int i = 0; i < 4; i++) inv[i] = 1.0f / l_[i];

    float o[4][4] = {};

    // ---------------- Pass B: weights + O ----------------
    for (int kt = 0; kt < TT / 64; kt++) {
        #pragma unroll
        for (int r = 0; r < 4; r++) {
            const int idx = t + r * 256;
            const int row = idx >> 4;
            const int c4  = (idx & 15) << 2;
            *(float4*)(KV + row * SST + c4) =
                *(const float4*)(Kg + (size_t)(kt * 64 + row) * DK + c4);
        }
        __syncthreads();

        float s[4][4] = {};
        #pragma unroll 8
        for (int kk = 0; kk < 64; kk++) {
            float ra[4], rb[4];
            #pragma unroll
            for (int i = 0; i < 4; i++) ra[i] = Qs[(ty * 4 + i) * SST + kk];
            #pragma unroll
            for (int j = 0; j < 4; j++) rb[j] = KV[(tx * 4 + j) * SST + kk];
            #pragma unroll
            for (int i = 0; i < 4; i++)
                #pragma unroll
                for (int j = 0; j < 4; j++)
                    s[i][j] = fmaf(ra[i], rb[j], s[i][j]);
        }

        // normalized weights
        #pragma unroll
        for (int i = 0; i < 4; i++) {
            float4 w4;
            w4.x = __expf(s[i][0] - m_[i]) * inv[i];
            w4.y = __expf(s[i][1] - m_[i]) * inv[i];
            w4.z = __expf(s[i][2] - m_[i]) * inv[i];
            w4.w = __expf(s[i][3] - m_[i]) * inv[i];
            *(float4*)(Ws + (ty * 4 + i) * SST + tx * 4) = w4;
            if (wout) {
                *(float4*)(wout + ((size_t)bh * TT + q0 + ty * 4 + i) * TT
                                 + kt * 64 + tx * 4) = w4;
            }
        }
        __syncthreads();   // KV(K) reads done, Ws visible

        // load V tile into KV
        #pragma unroll
        for (int r = 0; r < 4; r++) {
            const int idx = t + r * 256;
            const int row = idx >> 4;
            const int c4  = (idx & 15) << 2;
            *(float4*)(KV + row * SST + c4) =
                *(const float4*)(Vg + (size_t)(kt * 64 + row) * DK + c4);
        }
        __syncthreads();

        // O += Ws @ V
        #pragma unroll 8
        for (int j = 0; j < 64; j++) {
            float rw[4], rv[4];
            #pragma unroll
            for (int i = 0; i < 4; i++) rw[i] = Ws[(ty * 4 + i) * SST + j];
            #pragma unroll
            for (int c = 0; c < 4; c++) rv[c] = KV[j * SST + tx * 4 + c];
            #pragma unroll
            for (int i = 0; i < 4; i++)
                #pragma unroll
                for (int c = 0; c < 4; c++)
                    o[i][c] = fmaf(rw[i], rv[c], o[i][c]);
        }
        __syncthreads();
    }

    // write O to g_attn [B,T,D], e = h*64 + d
    const int b = bh >> 4;
    const int h = bh & 15;
    #pragma unroll
    for (int i = 0; i < 4; i++) {
        const int row = q0 + ty * 4 + i;
        float4 v = make_float4(o[i][0], o[i][1], o[i][2], o[i][3]);
        *(float4*)(g_attn + ((size_t)b * TT + row) * DD + h * DK + tx * 4) = v;
    }
}

// ---------------------------------------------------------------------------
extern "C" void kernel_launch(void* const* d_in, const int* in_sizes, int n_in,
                              void* d_out, int out_size)
{
    const float* query = (const float*)d_in[0];
    const float* key_  = (const float*)d_in[1];
    const float* value = (const float*)d_in[2];
    const float* W_q   = (const float*)d_in[3];
    const float* W_k   = (const float*)d_in[4];
    const float* W_v   = (const float*)d_in[5];
    const float* W_o   = (const float*)d_in[6];

    float *q_p, *k_p, *v_p, *a_p;
    cudaGetSymbolAddress((void**)&q_p, g_q);
    cudaGetSymbolAddress((void**)&k_p, g_k);
    cudaGetSymbolAddress((void**)&v_p, g_v);
    cudaGetSymbolAddress((void**)&a_p, g_attn);

    const dim3 pg(16, 64);   // N/64, M/64 for M=4096

    proj_kernel<<<pg, 256>>>(query, W_q, q_p, 1);
    proj_kernel<<<pg, 256>>>(key_,  W_k, k_p, 1);
    proj_kernel<<<pg, 256>>>(value, W_v, v_p, 1);

    const size_t OUT_E = (size_t)BB * TT * DD;                 // 4194304
    const size_t W_E   = (size_t)BB * HH * TT * (size_t)TT;    // 134217728
    float* wout = nullptr;
    if ((size_t)out_size >= OUT_E + W_E)
        wout = (float*)d_out + OUT_E;

    const int smem = 3 * 64 * SST * (int)sizeof(float);        // 52224 B
    cudaFuncSetAttribute(attn_kernel,
                         cudaFuncAttributeMaxDynamicSharedMemorySize, smem);
    attn_kernel<<<dim3(TT / 64, BB * HH), 256, smem>>>(wout);

    proj_kernel<<<pg, 256>>>(a_p, W_o, (float*)d_out, 0);
}

// round 3
// speedup vs baseline: 4.1279x; 4.1279x over previous
#include <cuda_runtime.h>
#include <cuda_bf16.h>
#include <math.h>

typedef unsigned int u32;

#define BB 2
#define TT 2048
#define DD 1024
#define HH 16
#define DK 64

// fp32 scratch (device globals; no allocations allowed)
__device__ float g_q[BB*HH*TT*DK];          // [B,H,T,DK]
__device__ float g_k[BB*HH*TT*DK];          // [B,H,T,DK]
__device__ float g_v[BB*HH*TT*DK];          // [B,H,T,DK]
__device__ float g_attn[(size_t)BB*TT*DD];  // [B,T,D]

// ---------------------------------------------------------------------------
// bf16 error-free-transform helpers
// ---------------------------------------------------------------------------
__device__ __forceinline__ void split2(float x0, float x1, u32 &h, u32 &l)
{
    __nv_bfloat162 hh = __floats2bfloat162_rn(x0, x1);     // low = x0
    float r0 = x0 - __bfloat162float(__low2bfloat16(hh));
    float r1 = x1 - __bfloat162float(__high2bfloat16(hh));
    __nv_bfloat162 ll = __floats2bfloat162_rn(r0, r1);
    h = *reinterpret_cast<u32*>(&hh);
    l = *reinterpret_cast<u32*>(&ll);
}

__device__ __forceinline__ void mma16816(float* c,
    u32 a0, u32 a1, u32 a2, u32 a3, u32 b0, u32 b1)
{
    asm volatile(
        "mma.sync.aligned.m16n8k16.row.col.f32.bf16.bf16.f32 "
        "{%0,%1,%2,%3},{%4,%5,%6,%7},{%8,%9},{%0,%1,%2,%3};"
        : "+f"(c[0]), "+f"(c[1]), "+f"(c[2]), "+f"(c[3])
        : "r"(a0), "r"(a1), "r"(a2), "r"(a3), "r"(b0), "r"(b1));
}

// ---------------------------------------------------------------------------
// Projection: C = A @ W^T.  A:[M,1024] rm, W:[1024,1024] rm ([out,in]).
// CTA tile 128x128, 8 warps (2m x 4n), warp tile 64x32, bf16x2 split MMA.
// perm==1: scatter to [B,H,T,DK]; perm==0: row-major [M,1024].
// ---------------------------------------------------------------------------
#define PJS 20   // smem row stride in b32 (16 payload + 4 pad)

__global__ void __launch_bounds__(256) proj_mma(const float* __restrict__ A,
                                                const float* __restrict__ W,
                                                float* __restrict__ C, int perm)
{
    __shared__ u32 Ah[128*PJS], Al[128*PJS], Bh[128*PJS], Bl[128*PJS];

    const int t = threadIdx.x;
    const int lane = t & 31, wid = t >> 5;
    const int g = lane >> 2, ctg = lane & 3;
    const int wm = wid >> 2, wn = wid & 3;          // 2 x 4 warps
    const int m0 = blockIdx.y * 128, n0 = blockIdx.x * 128;

    const int lr = t >> 1;                          // smem row 0..127
    const int lc = (t & 1) * 16;                    // float offset 0/16

    float c[4][4][4];
    #pragma unroll
    for (int i = 0; i < 4; i++)
        #pragma unroll
        for (int j = 0; j < 4; j++)
            #pragma unroll
            for (int r = 0; r < 4; r++) c[i][j][r] = 0.f;

    float4 pa[4], pb[4];
    #pragma unroll
    for (int u = 0; u < 4; u++) {
        pa[u] = *(const float4*)(A + (size_t)(m0 + lr) * 1024 + lc + u * 4);
        pb[u] = *(const float4*)(W + (size_t)(n0 + lr) * 1024 + lc + u * 4);
    }

    for (int k0 = 0; k0 < 1024; k0 += 32) {
        // stage regs -> smem (split to bf16 hi/lo)
        #pragma unroll
        for (int u = 0; u < 4; u++) {
            u32 h0, l0, h1, l1;
            const int bi = lr * PJS + (lc >> 1) + u * 2;
            split2(pa[u].x, pa[u].y, h0, l0); split2(pa[u].z, pa[u].w, h1, l1);
            Ah[bi] = h0; Ah[bi+1] = h1; Al[bi] = l0; Al[bi+1] = l1;
            split2(pb[u].x, pb[u].y, h0, l0); split2(pb[u].z, pb[u].w, h1, l1);
            Bh[bi] = h0; Bh[bi+1] = h1; Bl[bi] = l0; Bl[bi+1] = l1;
        }
        __syncthreads();

        if (k0 + 32 < 1024) {
            #pragma unroll
            for (int u = 0; u < 4; u++) {
                pa[u] = *(const float4*)(A + (size_t)(m0 + lr) * 1024 + k0 + 32 + lc + u * 4);
                pb[u] = *(const float4*)(W + (size_t)(n0 + lr) * 1024 + k0 + 32 + lc + u * 4);
            }
        }

        #pragma unroll
        for (int ch = 0; ch < 2; ch++) {
            const int kb = ch * 8 + ctg;
            u32 ah[4][4], al[4][4];
            #pragma unroll
            for (int i = 0; i < 4; i++) {
                const int r0 = (wm * 64 + i * 16 + g) * PJS;
                ah[i][0] = Ah[r0 + kb];           ah[i][1] = Ah[r0 + 8*PJS + kb];
                ah[i][2] = Ah[r0 + kb + 4];       ah[i][3] = Ah[r0 + 8*PJS + kb + 4];
                al[i][0] = Al[r0 + kb];           al[i][1] = Al[r0 + 8*PJS + kb];
                al[i][2] = Al[r0 + kb + 4];       al[i][3] = Al[r0 + 8*PJS + kb + 4];
            }
            #pragma unroll
            for (int j = 0; j < 4; j++) {
                const int nr = (wn * 32 + j * 8 + g) * PJS;
                const u32 b0h = Bh[nr + kb], b1h = Bh[nr + kb + 4];
                const u32 b0l = Bl[nr + kb], b1l = Bl[nr + kb + 4];
                #pragma unroll
                for (int i = 0; i < 4; i++) {
                    mma16816(c[i][j], ah[i][0], ah[i][1], ah[i][2], ah[i][3], b0h, b1h);
                    mma16816(c[i][j], ah[i][0], ah[i][1], ah[i][2], ah[i][3], b0l, b1l);
                    mma16816(c[i][j], al[i][0], al[i][1], al[i][2], al[i][3], b0h, b1h);
                }
            }
        }
        __syncthreads();
    }

    // epilogue
    #pragma unroll
    for (int i = 0; i < 4; i++) {
        #pragma unroll
        for (int h2 = 0; h2 < 2; h2++) {
            const int m = m0 + wm * 64 + i * 16 + h2 * 8 + g;
            #pragma unroll
            for (int j = 0; j < 4; j++) {
                const int n = n0 + wn * 32 + j * 8 + ctg * 2;
                float2 v = make_float2(c[i][j][h2*2], c[i][j][h2*2+1]);
                if (perm) {
                    const int b = m >> 11, tq = m & 2047;
                    const int h = n >> 6, dk = n & 63;
                    *(float2*)(C + (((size_t)(b * HH + h) * TT + tq) << 6) + dk) = v;
                } else {
                    *(float2*)(C + (size_t)m * 1024 + n) = v;
                }
            }
        }
    }
}

// ---------------------------------------------------------------------------
// Fused attention with bf16x2 MMA.
// CTA: 128 q-rows x one (b,h); key tiles of 128.  8 warps (4m x 2n).
// Pass A: online stats via S-MMA (per-warp HALF-row stats, merged via smem
// after the loop).  Pass B: recompute S, write normalized weights, AV-MMA.
// ---------------------------------------------------------------------------
#define QS 36   // Q/K row stride, b32 (32 payload + 4)
#define VS 68   // Vt row stride, b32 (64 payload + 4)
#define WS 68   // W  row stride, b32 (64 payload + 4)

extern __shared__ u32 smu[];

__global__ void __launch_bounds__(256) attn_mma(float* __restrict__ wout)
{
    u32* QH = smu;
    u32* QL = QH + 128 * QS;
    u32* KH = QL + 128 * QS;
    u32* KL = KH + 128 * QS;
    u32* VH = KL + 128 * QS;
    u32* VL = VH + 64 * VS;
    u32* WH = VL + 64 * VS;
    u32* WL = WH + 128 * WS;

    __shared__ float stats[128 * 4];   // per row: m(half0), l(half0), m(half1), l(half1)

    const int t = threadIdx.x, lane = t & 31, wid = t >> 5;
    const int g = lane >> 2, ctg = lane & 3;
    const int wm = wid >> 1, wn = wid & 1;          // 4 x 2 warps
    const int bh = blockIdx.y;
    const int q0 = blockIdx.x * 128;
    const int head = bh & 15, bb = bh >> 4;

    const float* Qg = g_q + (size_t)bh * TT * DK;
    const float* Kg = g_k + (size_t)bh * TT * DK;
    const float* Vg = g_v + (size_t)bh * TT * DK;

    const int lr = t >> 1;
    const int lc = (t & 1) * 32;

    // load Q tile (pre-scaled 1/sqrt(DK)=0.125), split
    #pragma unroll
    for (int u = 0; u < 8; u++) {
        float4 v = *(const float4*)(Qg + (size_t)(q0 + lr) * DK + lc + u * 4);
        u32 h0, l0, h1, l1;
        split2(v.x * 0.125f, v.y * 0.125f, h0, l0);
        split2(v.z * 0.125f, v.w * 0.125f, h1, l1);
        const int bi = lr * QS + ((lc + u * 4) >> 1);
        QH[bi] = h0; QH[bi+1] = h1; QL[bi] = l0; QL[bi+1] = l1;
    }

    float m_[4], l_[4];
    #pragma unroll
    for (int r = 0; r < 4; r++) { m_[r] = -1e30f; l_[r] = 0.f; }

    float4 pk[8];
    #pragma unroll
    for (int u = 0; u < 8; u++)
        pk[u] = *(const float4*)(Kg + (size_t)lr * DK + lc + u * 4);
    __syncthreads();   // Q visible

    // ============================ pass A: stats ============================
    for (int kt = 0; kt < 16; kt++) {
        #pragma unroll
        for (int u = 0; u < 8; u++) {
            u32 h0, l0, h1, l1;
            split2(pk[u].x, pk[u].y, h0, l0); split2(pk[u].z, pk[u].w, h1, l1);
            const int bi = lr * QS + ((lc + u * 4) >> 1);
            KH[bi] = h0; KH[bi+1] = h1; KL[bi] = l0; KL[bi+1] = l1;
        }
        __syncthreads();
        if (kt < 15) {
            #pragma unroll
            for (int u = 0; u < 8; u++)
                pk[u] = *(const float4*)(Kg + (size_t)((kt+1)*128 + lr) * DK + lc + u * 4);
        }

        float s[2][8][4];
        #pragma unroll
        for (int i = 0; i < 2; i++)
            #pragma unroll
            for (int j = 0; j < 8; j++)
                #pragma unroll
                for (int r = 0; r < 4; r++) s[i][j][r] = 0.f;

        #pragma unroll
        for (int ch = 0; ch < 4; ch++) {
            const int kb = ch * 8 + ctg;
            u32 ah[2][4], al[2][4];
            #pragma unroll
            for (int i = 0; i < 2; i++) {
                const int r0 = (wm * 32 + i * 16 + g) * QS;
                ah[i][0] = QH[r0 + kb];         ah[i][1] = QH[r0 + 8*QS + kb];
                ah[i][2] = QH[r0 + kb + 4];     ah[i][3] = QH[r0 + 8*QS + kb + 4];
                al[i][0] = QL[r0 + kb];         al[i][1] = QL[r0 + 8*QS + kb];
                al[i][2] = QL[r0 + kb + 4];     al[i][3] = QL[r0 + 8*QS + kb + 4];
            }
            #pragma unroll
            for (int j = 0; j < 8; j++) {
                const int nr = (wn * 64 + j * 8 + g) * QS;
                const u32 b0h = KH[nr + kb], b1h = KH[nr + kb + 4];
                const u32 b0l = KL[nr + kb], b1l = KL[nr + kb + 4];
                #pragma unroll
                for (int i = 0; i < 2; i++) {
                    mma16816(s[i][j], ah[i][0], ah[i][1], ah[i][2], ah[i][3], b0h, b1h);
                    mma16816(s[i][j], ah[i][0], ah[i][1], ah[i][2], ah[i][3], b0l, b1l);
                    mma16816(s[i][j], al[i][0], al[i][1], al[i][2], al[i][3], b0h, b1h);
                }
            }
        }

        #pragma unroll
        for (int i = 0; i < 2; i++)
            #pragma unroll
            for (int h2 = 0; h2 < 2; h2++) {
                const int idx = i * 2 + h2;
                float tm = -1e30f;
                #pragma unroll
                for (int j = 0; j < 8; j++)
                    tm = fmaxf(tm, fmaxf(s[i][j][h2*2], s[i][j][h2*2+1]));
                tm = fmaxf(tm, __shfl_xor_sync(0xffffffffu, tm, 1));
                tm = fmaxf(tm, __shfl_xor_sync(0xffffffffu, tm, 2));
                const float nm = fmaxf(m_[idx], tm);
                float sum = 0.f;
                #pragma unroll
                for (int j = 0; j < 8; j++)
                    sum += __expf(s[i][j][h2*2] - nm) + __expf(s[i][j][h2*2+1] - nm);
                sum += __shfl_xor_sync(0xffffffffu, sum, 1);
                sum += __shfl_xor_sync(0xffffffffu, sum, 2);
                l_[idx] = l_[idx] * __expf(m_[idx] - nm) + sum;
                m_[idx] = nm;
            }
        __syncthreads();
    }

    // ---- merge the two warp-column-halves' stats per row ----
    if (ctg == 0) {
        #pragma unroll
        for (int i = 0; i < 2; i++)
            #pragma unroll
            for (int h2 = 0; h2 < 2; h2++) {
                const int idx = i * 2 + h2;
                const int row = wm * 32 + i * 16 + h2 * 8 + g;
                stats[row * 4 + wn * 2 + 0] = m_[idx];
                stats[row * 4 + wn * 2 + 1] = l_[idx];
            }
    }
    __syncthreads();
    float inv[4];
    #pragma unroll
    for (int i = 0; i < 2; i++)
        #pragma unroll
        for (int h2 = 0; h2 < 2; h2++) {
            const int idx = i * 2 + h2;
            const int row = wm * 32 + i * 16 + h2 * 8 + g;
            const float m0 = stats[row*4+0], L0 = stats[row*4+1];
            const float m1 = stats[row*4+2], L1 = stats[row*4+3];
            const float M = fmaxf(m0, m1);
            const float L = L0 * __expf(m0 - M) + L1 * __expf(m1 - M);
            m_[idx] = M; l_[idx] = L; inv[idx] = 1.f / L;
        }

    float o[2][4][4];
    #pragma unroll
    for (int i = 0; i < 2; i++)
        #pragma unroll
        for (int j = 0; j < 4; j++)
            #pragma unroll
            for (int r = 0; r < 4; r++) o[i][j][r] = 0.f;

    #pragma unroll
    for (int u = 0; u < 8; u++)
        pk[u] = *(const float4*)(Kg + (size_t)lr * DK + lc + u * 4);

    // ====================== pass B: weights + O ======================
    for (int kt = 0; kt < 16; kt++) {
        #pragma unroll
        for (int u = 0; u < 8; u++) {
            u32 h0, l0, h1, l1;
            split2(pk[u].x, pk[u].y, h0, l0); split2(pk[u].z, pk[u].w, h1, l1);
            const int bi = lr * QS + ((lc + u * 4) >> 1);
            KH[bi] = h0; KH[bi+1] = h1; KL[bi] = l0; KL[bi+1] = l1;
        }
        __syncthreads();
        if (kt < 15) {
            #pragma unroll
            for (int u = 0; u < 8; u++)
                pk[u] = *(const float4*)(Kg + (size_t)((kt+1)*128 + lr) * DK + lc + u * 4);
        }

        float s[2][8][4];
        #pragma unroll
        for (int i = 0; i < 2; i++)
            #pragma unroll
            for (int j = 0; j < 8; j++)
                #pragma unroll
                for (int r = 0; r < 4; r++) s[i][j][r] = 0.f;

        #pragma unroll
        for (int ch = 0; ch < 4; ch++) {
            const int kb = ch * 8 + ctg;
            u32 ah[2][4], al[2][4];
            #pragma unroll
            for (int i = 0; i < 2; i++) {
                const int r0 = (wm * 32 + i * 16 + g) * QS;
                ah[i][0] = QH[r0 + kb];         ah[i][1] = QH[r0 + 8*QS + kb];
                ah[i][2] = QH[r0 + kb + 4];     ah[i][3] = QH[r0 + 8*QS + kb + 4];
                al[i][0] = QL[r0 + kb];         al[i][1] = QL[r0 + 8*QS + kb];
                al[i][2] = QL[r0 + kb + 4];     al[i][3] = QL[r0 + 8*QS + kb + 4];
            }
            #pragma unroll
            for (int j = 0; j < 8; j++) {
                const int nr = (wn * 64 + j * 8 + g) * QS;
                const u32 b0h = KH[nr + kb], b1h = KH[nr + kb + 4];
                const u32 b0l = KL[nr + kb], b1l = KL[nr + kb + 4];
                #pragma unroll
                for (int i = 0; i < 2; i++) {
                    mma16816(s[i][j], ah[i][0], ah[i][1], ah[i][2], ah[i][3], b0h, b1h);
                    mma16816(s[i][j], ah[i][0], ah[i][1], ah[i][2], ah[i][3], b0l, b1l);
                    mma16816(s[i][j], al[i][0], al[i][1], al[i][2], al[i][3], b0h, b1h);
                }
            }
        }

        // W = softmax weights: write gmem + split into smem for AV
        #pragma unroll
        for (int i = 0; i < 2; i++)
            #pragma unroll
            for (int h2 = 0; h2 < 2; h2++) {
                const int idx = i * 2 + h2;
                const int row = wm * 32 + i * 16 + h2 * 8 + g;
                #pragma unroll
                for (int j = 0; j < 8; j++) {
                    const float w0 = __expf(s[i][j][h2*2]   - m_[idx]) * inv[idx];
                    const float w1 = __expf(s[i][j][h2*2+1] - m_[idx]) * inv[idx];
                    if (wout)
                        *(float2*)(wout + ((size_t)bh * TT + q0 + row) * TT
                                        + kt * 128 + wn * 64 + j * 8 + ctg * 2)
                            = make_float2(w0, w1);
                    u32 h, l;
                    split2(w0, w1, h, l);
                    WH[row * WS + wn * 32 + j * 4 + ctg] = h;
                    WL[row * WS + wn * 32 + j * 4 + ctg] = l;
                }
            }

        // V tile load + transpose into Vt[dk][key-pairs]
        #pragma unroll
        for (int u = 0; u < 4; u++) {
            const int idx = t + u * 256;
            const int kp = idx & 63, dc = idx >> 6;   // keypair, dk-chunk
            const float* p = Vg + (size_t)(kt * 128 + kp * 2) * DK + dc * 4;
            float4 v0 = *(const float4*)p;
            float4 v1 = *(const float4*)(p + DK);
            const float a0[4] = {v0.x, v0.y, v0.z, v0.w};
            const float a1[4] = {v1.x, v1.y, v1.z, v1.w};
            #pragma unroll
            for (int e = 0; e < 4; e++) {
                u32 h, l;
                split2(a0[e], a1[e], h, l);
                VH[(dc * 4 + e) * VS + kp] = h;
                VL[(dc * 4 + e) * VS + kp] = l;
            }
        }
        __syncthreads();

        // O += W @ V
        #pragma unroll
        for (int ch = 0; ch < 8; ch++) {
            const int kb = ch * 8 + ctg;
            u32 ah[2][4], al[2][4];
            #pragma unroll
            for (int i = 0; i < 2; i++) {
                const int r0 = (wm * 32 + i * 16 + g) * WS;
                ah[i][0] = WH[r0 + kb];         ah[i][1] = WH[r0 + 8*WS + kb];
                ah[i][2] = WH[r0 + kb + 4];     ah[i][3] = WH[r0 + 8*WS + kb + 4];
                al[i][0] = WL[r0 + kb];         al[i][1] = WL[r0 + 8*WS + kb];
                al[i][2] = WL[r0 + kb + 4];     al[i][3] = WL[r0 + 8*WS + kb + 4];
            }
            #pragma unroll
            for (int j = 0; j < 4; j++) {
                const int nr = (wn * 32 + j * 8 + g) * VS;
                const u32 b0h = VH[nr + kb], b1h = VH[nr + kb + 4];
                const u32 b0l = VL[nr + kb], b1l = VL[nr + kb + 4];
                #pragma unroll
                for (int i = 0; i < 2; i++) {
                    mma16816(o[i][j], ah[i][0], ah[i][1], ah[i][2], ah[i][3], b0h, b1h);
                    mma16816(o[i][j], ah[i][0], ah[i][1], ah[i][2], ah[i][3], b0l, b1l);
                    mma16816(o[i][j], al[i][0], al[i][1], al[i][2], al[i][3], b0h, b1h);
                }
            }
        }
    }

    // epilogue: O -> g_attn [B,T,D]
    #pragma unroll
    for (int i = 0; i < 2; i++)
        #pragma unroll
        for (int h2 = 0; h2 < 2; h2++) {
            const int row = q0 + wm * 32 + i * 16 + h2 * 8 + g;
            #pragma unroll
            for (int j = 0; j < 4; j++) {
                const int col = head * 64 + wn * 32 + j * 8 + ctg * 2;
                float2 v = make_float2(o[i][j][h2*2], o[i][j][h2*2+1]);
                *(float2*)(g_attn + ((size_t)bb * TT + row) * DD + col) = v;
            }
        }
}

// ---------------------------------------------------------------------------
extern "C" void kernel_launch(void* const* d_in, const int* in_sizes, int n_in,
                              void* d_out, int out_size)
{
    const float* query = (const float*)d_in[0];
    const float* key_  = (const float*)d_in[1];
    const float* value = (const float*)d_in[2];
    const float* W_q   = (const float*)d_in[3];
    const float* W_k   = (const float*)d_in[4];
    const float* W_v   = (const float*)d_in[5];
    const float* W_o   = (const float*)d_in[6];

    float *q_p, *k_p, *v_p, *a_p;
    cudaGetSymbolAddress((void**)&q_p, g_q);
    cudaGetSymbolAddress((void**)&k_p, g_k);
    cudaGetSymbolAddress((void**)&v_p, g_v);
    cudaGetSymbolAddress((void**)&a_p, g_attn);

    const dim3 pg(1024 / 128, (BB * TT) / 128);   // (8, 32)

    proj_mma<<<pg, 256>>>(query, W_q, q_p, 1);
    proj_mma<<<pg, 256>>>(key_,  W_k, k_p, 1);
    proj_mma<<<pg, 256>>>(value, W_v, v_p, 1);

    const size_t OUT_E = (size_t)BB * TT * DD;
    const size_t W_E   = (size_t)BB * HH * TT * (size_t)TT;
    float* wout = nullptr;
    if ((size_t)out_size >= OUT_E + W_E)
        wout = (float*)d_out + OUT_E;

    const int smem = (4 * 128 * QS + 2 * 64 * VS + 2 * 128 * WS) * (int)sizeof(u32);
    cudaFuncSetAttribute(attn_mma,
                         cudaFuncAttributeMaxDynamicSharedMemorySize, smem);
    attn_mma<<<dim3(TT / 128, BB * HH), 256, smem>>>(wout);

    proj_mma<<<pg, 256>>>(a_p, W_o, (float*)d_out, 0);
}

// round 4
// speedup vs baseline: 4.8302x; 1.1701x over previous
#include <cuda_runtime.h>
#include <cuda_bf16.h>
#include <math.h>

typedef unsigned int u32;

#define BB 2
#define TT 2048
#define DD 1024
#define HH 16
#define DK 64

#define SEG  4194304          // B*T*D
#define WSEG 1048576          // D*D
// scratch layout (bf16 elements) in g_sh/g_sl:
//  0:qin  SEG:kin  2S:vin  3S:wq  3S+W:wk  3S+2W:wv  3S+3W:wo
//  4S:Q[B,H,T,DK]  5S:K  6S:V  7S:attn[B,T,D]
__device__ __align__(16) __nv_bfloat16 g_sh[8 * SEG];
__device__ __align__(16) __nv_bfloat16 g_sl[8 * SEG];

// ---------------------------------------------------------------------------
__device__ __forceinline__ void split2(float x0, float x1, u32 &h, u32 &l)
{
    __nv_bfloat162 hh = __floats2bfloat162_rn(x0, x1);
    float r0 = x0 - __bfloat162float(__low2bfloat16(hh));
    float r1 = x1 - __bfloat162float(__high2bfloat16(hh));
    __nv_bfloat162 ll = __floats2bfloat162_rn(r0, r1);
    h = *reinterpret_cast<u32*>(&hh);
    l = *reinterpret_cast<u32*>(&ll);
}

__device__ __forceinline__ void mma16816(float* c,
    u32 a0, u32 a1, u32 a2, u32 a3, u32 b0, u32 b1)
{
    asm volatile(
        "mma.sync.aligned.m16n8k16.row.col.f32.bf16.bf16.f32 "
        "{%0,%1,%2,%3},{%4,%5,%6,%7},{%8,%9},{%0,%1,%2,%3};"
        : "+f"(c[0]), "+f"(c[1]), "+f"(c[2]), "+f"(c[3])
        : "r"(a0), "r"(a1), "r"(a2), "r"(a3), "r"(b0), "r"(b1));
}

__device__ __forceinline__ void ldsm4(u32* r, u32 addr)
{
    asm volatile("ldmatrix.sync.aligned.m8n8.x4.shared.b16 {%0,%1,%2,%3}, [%4];"
        : "=r"(r[0]), "=r"(r[1]), "=r"(r[2]), "=r"(r[3]) : "r"(addr));
}
__device__ __forceinline__ void ldsm4t(u32* r, u32 addr)
{
    asm volatile("ldmatrix.sync.aligned.m8n8.x4.trans.shared.b16 {%0,%1,%2,%3}, [%4];"
        : "=r"(r[0]), "=r"(r[1]), "=r"(r[2]), "=r"(r[3]) : "r"(addr));
}

// ---------------------------------------------------------------------------
// Split all 7 fp32 inputs into bf16 hi/lo scratch.
// ---------------------------------------------------------------------------
__global__ void split_inputs(const float* q, const float* k, const float* v,
                             const float* wq, const float* wk, const float* wv,
                             const float* wo)
{
    const float* srcs[7] = {q, k, v, wq, wk, wv, wo};
    const int offs[7] = {0, SEG, 2*SEG, 3*SEG, 3*SEG+WSEG, 3*SEG+2*WSEG, 3*SEG+3*WSEG};
    const int cnts[7] = {SEG, SEG, SEG, WSEG, WSEG, WSEG, WSEG};
    const int sid = blockIdx.y;
    const float* src = srcs[sid];
    const int off = offs[sid], cnt = cnts[sid];
    for (int idx = (blockIdx.x * 256 + threadIdx.x) * 4; idx < cnt;
         idx += gridDim.x * 1024) {
        float4 x = *(const float4*)(src + idx);
        u32 h0, l0, h1, l1;
        split2(x.x, x.y, h0, l0);
        split2(x.z, x.w, h1, l1);
        *(u32*)(g_sh + off + idx)     = h0;
        *(u32*)(g_sh + off + idx + 2) = h1;
        *(u32*)(g_sl + off + idx)     = l0;
        *(u32*)(g_sl + off + idx + 2) = l1;
    }
}

// ---------------------------------------------------------------------------
// Projection GEMM in split bf16: C = A @ W^T.
// qkv=1: z=blockIdx.z in {0,1,2} -> Q/K/V (split-bf16 out, [B,H,T,DK], Q scaled).
// qkv=0: z=3 -> O projection (fp32 out [M,1024]).
// CTA 128x128, k-tile 32, 8 warps (2m x 4n), ldmatrix + 3-MMA EFT.
// ---------------------------------------------------------------------------
#define PJS 20   // smem row stride in u32 (32 bf16 payload + 8 pad)

__global__ void __launch_bounds__(256) proj_mma(float* __restrict__ fout, int qkv)
{
    __shared__ u32 smem[4 * 128 * PJS];

    const int z = qkv ? blockIdx.z : 3;
    const int aoff = (z == 3) ? 7 * SEG : z * SEG;
    const int woff = 3 * SEG + z * WSEG;
    const __nv_bfloat16* Ah = g_sh + aoff;
    const __nv_bfloat16* Al = g_sl + aoff;
    const __nv_bfloat16* Bh = g_sh + woff;
    const __nv_bfloat16* Bl = g_sl + woff;

    const int t = threadIdx.x, lane = t & 31, wid = t >> 5;
    const int g = lane >> 2, ctg = lane & 3;
    const int wm = wid >> 2, wn = wid & 3;
    const int m0 = blockIdx.y * 128, n0 = blockIdx.x * 128;

    const u32 sb = (u32)__cvta_generic_to_shared(smem);
    const u32 bAh = sb, bAl = sb + 10240, bBh = sb + 20480, bBl = sb + 30720;
    u32* sAh = smem;         u32* sAl = smem + 2560;
    u32* sBh = smem + 5120;  u32* sBl = smem + 7680;

    const u32 lro = ((lane & 7) + ((lane >> 3) & 1) * 8) * 80 + (lane >> 4) * 16;

    const int qq0 = t, qq1 = t + 256;          // uint4 idx in [0,512)
    const int r0_ = qq0 >> 2, sg0 = qq0 & 3;
    const int r1_ = qq1 >> 2, sg1 = qq1 & 3;

    float c[4][4][4];
    #pragma unroll
    for (int i = 0; i < 4; i++)
        #pragma unroll
        for (int j = 0; j < 4; j++)
            #pragma unroll
            for (int r = 0; r < 4; r++) c[i][j][r] = 0.f;

    uint4 pa[8];
    #pragma unroll
    for (int p = 0; p < 4; p++) {
        const __nv_bfloat16* base = (p == 0) ? Ah : (p == 1) ? Al : (p == 2) ? Bh : Bl;
        const int row0 = (p < 2) ? m0 : n0;
        pa[p*2+0] = *(const uint4*)(base + (size_t)(row0 + r0_) * 1024 + sg0 * 8);
        pa[p*2+1] = *(const uint4*)(base + (size_t)(row0 + r1_) * 1024 + sg1 * 8);
    }

    for (int k0 = 0; k0 < 1024; k0 += 32) {
        #pragma unroll
        for (int p = 0; p < 4; p++) {
            u32* dst = (p == 0) ? sAh : (p == 1) ? sAl : (p == 2) ? sBh : sBl;
            *(uint4*)(dst + r0_ * PJS + sg0 * 4) = pa[p*2+0];
            *(uint4*)(dst + r1_ * PJS + sg1 * 4) = pa[p*2+1];
        }
        __syncthreads();

        if (k0 + 32 < 1024) {
            #pragma unroll
            for (int p = 0; p < 4; p++) {
                const __nv_bfloat16* base = (p == 0) ? Ah : (p == 1) ? Al : (p == 2) ? Bh : Bl;
                const int row0 = (p < 2) ? m0 : n0;
                pa[p*2+0] = *(const uint4*)(base + (size_t)(row0 + r0_) * 1024 + k0 + 32 + sg0 * 8);
                pa[p*2+1] = *(const uint4*)(base + (size_t)(row0 + r1_) * 1024 + k0 + 32 + sg1 * 8);
            }
        }

        #pragma unroll
        for (int ch = 0; ch < 2; ch++) {
            u32 a[4][2][4];
            #pragma unroll
            for (int i = 0; i < 4; i++) {
                const u32 ad = (u32)(wm * 64 + i * 16) * 80 + ch * 32 + lro;
                ldsm4(a[i][0], bAh + ad);
                ldsm4(a[i][1], bAl + ad);
            }
            u32 bh_[2][4], bl_[2][4];
            #pragma unroll
            for (int jp = 0; jp < 2; jp++) {
                const u32 bd = (u32)(wn * 32 + jp * 16) * 80 + ch * 32 + lro;
                ldsm4(bh_[jp], bBh + bd);
                ldsm4(bl_[jp], bBl + bd);
            }
            #pragma unroll
            for (int jp = 0; jp < 2; jp++)
                #pragma unroll
                for (int jj = 0; jj < 2; jj++) {
                    const int j = jp * 2 + jj;
                    const u32 b0h = bh_[jp][jj], b1h = bh_[jp][2 + jj];
                    const u32 b0l = bl_[jp][jj], b1l = bl_[jp][2 + jj];
                    #pragma unroll
                    for (int i = 0; i < 4; i++) {
                        mma16816(c[i][j], a[i][0][0], a[i][0][1], a[i][0][2], a[i][0][3], b0h, b1h);
                        mma16816(c[i][j], a[i][0][0], a[i][0][1], a[i][0][2], a[i][0][3], b0l, b1l);
                        mma16816(c[i][j], a[i][1][0], a[i][1][1], a[i][1][2], a[i][1][3], b0h, b1h);
                    }
                }
        }
        __syncthreads();
    }

    // epilogue
    const float scale = (z == 0) ? 0.125f : 1.0f;
    if (z < 3) {
        __nv_bfloat16* Oh = g_sh + (4 + z) * SEG;
        __nv_bfloat16* Ol = g_sl + (4 + z) * SEG;
        #pragma unroll
        for (int i = 0; i < 4; i++)
            #pragma unroll
            for (int h2 = 0; h2 < 2; h2++) {
                const int m = m0 + wm * 64 + i * 16 + h2 * 8 + g;
                const int b = m >> 11, tq = m & 2047;
                #pragma unroll
                for (int j = 0; j < 4; j++) {
                    const int n = n0 + wn * 32 + j * 8 + ctg * 2;
                    const int h = n >> 6, dk = n & 63;
                    u32 hi, lo;
                    split2(c[i][j][h2*2] * scale, c[i][j][h2*2+1] * scale, hi, lo);
                    const size_t e = (((size_t)(b * HH + h) * TT + tq) << 6) + dk;
                    *(u32*)(Oh + e) = hi;
                    *(u32*)(Ol + e) = lo;
                }
            }
    } else {
        #pragma unroll
        for (int i = 0; i < 4; i++)
            #pragma unroll
            for (int h2 = 0; h2 < 2; h2++) {
                const int m = m0 + wm * 64 + i * 16 + h2 * 8 + g;
                #pragma unroll
                for (int j = 0; j < 4; j++) {
                    const int n = n0 + wn * 32 + j * 8 + ctg * 2;
                    *(float2*)(fout + (size_t)m * 1024 + n)
                        = make_float2(c[i][j][h2*2], c[i][j][h2*2+1]);
                }
            }
    }
}

// ---------------------------------------------------------------------------
// Fused attention, split-bf16 IO, ldmatrix, fixed-shift softmax.
// CTA = 128 q-rows of one (b,h); 8 warps (4m x 2n); key tiles of 128.
// Pass A: row sums of exp(s). Pass B: S again, normalized weights out, AV.
// smem (u32 units): Qh 0, Ql 4608, Kh 9216, Kl 13824, Vh 18432, Vl 23040,
//                   Wh 27648, Wl 36352; total 45056 u32 = 180224 B.
// ---------------------------------------------------------------------------
extern __shared__ u32 sm_a[];

__global__ void __launch_bounds__(256) attn_mma(float* __restrict__ wout)
{
    __shared__ float stats[256];   // [row][wn]

    const int t = threadIdx.x, lane = t & 31, wid = t >> 5;
    const int g = lane >> 2, ctg = lane & 3;
    const int wm = wid >> 1, wn = wid & 1;
    const int bh = blockIdx.y;
    const int q0 = blockIdx.x * 128;
    const int head = bh & 15, bb = bh >> 4;

    const __nv_bfloat16* Qgh = g_sh + 4 * SEG + (size_t)bh * TT * DK;
    const __nv_bfloat16* Qgl = g_sl + 4 * SEG + (size_t)bh * TT * DK;
    const __nv_bfloat16* Kgh = g_sh + 5 * SEG + (size_t)bh * TT * DK;
    const __nv_bfloat16* Kgl = g_sl + 5 * SEG + (size_t)bh * TT * DK;
    const __nv_bfloat16* Vgh = g_sh + 6 * SEG + (size_t)bh * TT * DK;
    const __nv_bfloat16* Vgl = g_sl + 6 * SEG + (size_t)bh * TT * DK;

    const u32 sb = (u32)__cvta_generic_to_shared(sm_a);
    const u32 bQh = sb,          bQl = sb + 18432;
    const u32 bKh = sb + 36864,  bKl = sb + 55296;
    const u32 bVh = sb + 73728,  bVl = sb + 92160;
    const u32 bWh = sb + 110592, bWl = sb + 145408;
    u32* sQh = sm_a;          u32* sQl = sm_a + 4608;
    u32* sKh = sm_a + 9216;   u32* sKl = sm_a + 13824;
    u32* sVh = sm_a + 18432;  u32* sVl = sm_a + 23040;
    u32* sWh = sm_a + 27648;  u32* sWl = sm_a + 36352;

    const u32 lro36 = ((lane & 7) + ((lane >> 3) & 1) * 8) * 144 + (lane >> 4) * 16;
    const u32 lro68 = ((lane & 7) + ((lane >> 3) & 1) * 8) * 272 + (lane >> 4) * 16;

    // ---- load Q tile (split) ----
    #pragma unroll
    for (int j = 0; j < 8; j++) {
        const int sel = j >> 2;
        const int qq = t + (j & 3) * 256;        // uint4 idx [0,1024)
        const int r = qq >> 3, sg = qq & 7;
        const uint4 v = *(const uint4*)((sel ? Qgl : Qgh) + (size_t)(q0 + r) * DK + sg * 8);
        *(uint4*)((sel ? sQl : sQh) + r * 36 + sg * 4) = v;
    }

    float l_[4] = {0.f, 0.f, 0.f, 0.f};

    uint4 pk[8];
    #pragma unroll
    for (int j = 0; j < 8; j++) {
        const int sel = j >> 2;
        const int qq = t + (j & 3) * 256;
        const int r = qq >> 3, sg = qq & 7;
        pk[j] = *(const uint4*)((sel ? Kgl : Kgh) + (size_t)r * DK + sg * 8);
    }

    // ============================ pass A ============================
    for (int kt = 0; kt < 16; kt++) {
        #pragma unroll
        for (int j = 0; j < 8; j++) {
            const int sel = j >> 2;
            const int qq = t + (j & 3) * 256;
            const int r = qq >> 3, sg = qq & 7;
            *(uint4*)((sel ? sKl : sKh) + r * 36 + sg * 4) = pk[j];
        }
        __syncthreads();
        if (kt < 15) {
            #pragma unroll
            for (int j = 0; j < 8; j++) {
                const int sel = j >> 2;
                const int qq = t + (j & 3) * 256;
                const int r = qq >> 3, sg = qq & 7;
                pk[j] = *(const uint4*)((sel ? Kgl : Kgh) + (size_t)((kt + 1) * 128 + r) * DK + sg * 8);
            }
        }

        float s[2][8][4];
        #pragma unroll
        for (int i = 0; i < 2; i++)
            #pragma unroll
            for (int j = 0; j < 8; j++)
                #pragma unroll
                for (int r = 0; r < 4; r++) s[i][j][r] = 0.f;

        #pragma unroll
        for (int ch = 0; ch < 4; ch++) {
            u32 a[2][2][4];
            #pragma unroll
            for (int i = 0; i < 2; i++) {
                const u32 ad = (u32)(wm * 32 + i * 16) * 144 + ch * 32 + lro36;
                ldsm4(a[i][0], bQh + ad);
                ldsm4(a[i][1], bQl + ad);
            }
            #pragma unroll
            for (int jp = 0; jp < 4; jp++) {
                u32 bfh[4], bfl[4];
                const u32 bd = (u32)(wn * 64 + jp * 16) * 144 + ch * 32 + lro36;
                ldsm4(bfh, bKh + bd);
                ldsm4(bfl, bKl + bd);
                #pragma unroll
                for (int jj = 0; jj < 2; jj++) {
                    const int j = jp * 2 + jj;
                    const u32 b0h = bfh[jj], b1h = bfh[2 + jj];
                    const u32 b0l = bfl[jj], b1l = bfl[2 + jj];
                    #pragma unroll
                    for (int i = 0; i < 2; i++) {
                        mma16816(s[i][j], a[i][0][0], a[i][0][1], a[i][0][2], a[i][0][3], b0h, b1h);
                        mma16816(s[i][j], a[i][0][0], a[i][0][1], a[i][0][2], a[i][0][3], b0l, b1l);
                        mma16816(s[i][j], a[i][1][0], a[i][1][1], a[i][1][2], a[i][1][3], b0h, b1h);
                    }
                }
            }
        }

        #pragma unroll
        for (int i = 0; i < 2; i++)
            #pragma unroll
            for (int h2 = 0; h2 < 2; h2++) {
                float sum = 0.f;
                #pragma unroll
                for (int j = 0; j < 8; j++)
                    sum += __expf(s[i][j][h2*2]) + __expf(s[i][j][h2*2+1]);
                sum += __shfl_xor_sync(0xffffffffu, sum, 1);
                sum += __shfl_xor_sync(0xffffffffu, sum, 2);
                l_[i * 2 + h2] += sum;
            }
        __syncthreads();
    }

    // ---- merge wn halves: plain add (fixed shift) ----
    if (ctg == 0) {
        #pragma unroll
        for (int i = 0; i < 2; i++)
            #pragma unroll
            for (int h2 = 0; h2 < 2; h2++) {
                const int row = wm * 32 + i * 16 + h2 * 8 + g;
                stats[row * 2 + wn] = l_[i * 2 + h2];
            }
    }
    __syncthreads();
    float inv[4];
    #pragma unroll
    for (int i = 0; i < 2; i++)
        #pragma unroll
        for (int h2 = 0; h2 < 2; h2++) {
            const int row = wm * 32 + i * 16 + h2 * 8 + g;
            inv[i * 2 + h2] = 1.f / (stats[row * 2 + 0] + stats[row * 2 + 1]);
        }

    float o[2][4][4];
    #pragma unroll
    for (int i = 0; i < 2; i++)
        #pragma unroll
        for (int j = 0; j < 4; j++)
            #pragma unroll
            for (int r = 0; r < 4; r++) o[i][j][r] = 0.f;

    #pragma unroll
    for (int j = 0; j < 8; j++) {
        const int sel = j >> 2;
        const int qq = t + (j & 3) * 256;
        const int r = qq >> 3, sg = qq & 7;
        pk[j] = *(const uint4*)((sel ? Kgl : Kgh) + (size_t)r * DK + sg * 8);
    }

    // ============================ pass B ============================
    for (int kt = 0; kt < 16; kt++) {
        #pragma unroll
        for (int j = 0; j < 8; j++) {
            const int sel = j >> 2;
            const int qq = t + (j & 3) * 256;
            const int r = qq >> 3, sg = qq & 7;
            *(uint4*)((sel ? sKl : sKh) + r * 36 + sg * 4) = pk[j];
        }
        __syncthreads();
        if (kt < 15) {
            #pragma unroll
            for (int j = 0; j < 8; j++) {
                const int sel = j >> 2;
                const int qq = t + (j & 3) * 256;
                const int r = qq >> 3, sg = qq & 7;
                pk[j] = *(const uint4*)((sel ? Kgl : Kgh) + (size_t)((kt + 1) * 128 + r) * DK + sg * 8);
            }
        }
        // V tile for CURRENT kt: issue early, store after S (latency hidden)
        uint4 pv[8];
        #pragma unroll
        for (int j = 0; j < 8; j++) {
            const int sel = j >> 2;
            const int qq = t + (j & 3) * 256;
            const int r = qq >> 3, sg = qq & 7;
            pv[j] = *(const uint4*)((sel ? Vgl : Vgh) + (size_t)(kt * 128 + r) * DK + sg * 8);
        }

        float s[2][8][4];
        #pragma unroll
        for (int i = 0; i < 2; i++)
            #pragma unroll
            for (int j = 0; j < 8; j++)
                #pragma unroll
                for (int r = 0; r < 4; r++) s[i][j][r] = 0.f;

        #pragma unroll
        for (int ch = 0; ch < 4; ch++) {
            u32 a[2][2][4];
            #pragma unroll
            for (int i = 0; i < 2; i++) {
                const u32 ad = (u32)(wm * 32 + i * 16) * 144 + ch * 32 + lro36;
                ldsm4(a[i][0], bQh + ad);
                ldsm4(a[i][1], bQl + ad);
            }
            #pragma unroll
            for (int jp = 0; jp < 4; jp++) {
                u32 bfh[4], bfl[4];
                const u32 bd = (u32)(wn * 64 + jp * 16) * 144 + ch * 32 + lro36;
                ldsm4(bfh, bKh + bd);
                ldsm4(bfl, bKl + bd);
                #pragma unroll
                for (int jj = 0; jj < 2; jj++) {
                    const int j = jp * 2 + jj;
                    const u32 b0h = bfh[jj], b1h = bfh[2 + jj];
                    const u32 b0l = bfl[jj], b1l = bfl[2 + jj];
                    #pragma unroll
                    for (int i = 0; i < 2; i++) {
                        mma16816(s[i][j], a[i][0][0], a[i][0][1], a[i][0][2], a[i][0][3], b0h, b1h);
                        mma16816(s[i][j], a[i][0][0], a[i][0][1], a[i][0][2], a[i][0][3], b0l, b1l);
                        mma16816(s[i][j], a[i][1][0], a[i][1][1], a[i][1][2], a[i][1][3], b0h, b1h);
                    }
                }
            }
        }

        // normalized weights: gmem + split into W smem
        #pragma unroll
        for (int i = 0; i < 2; i++)
            #pragma unroll
            for (int h2 = 0; h2 < 2; h2++) {
                const int idx = i * 2 + h2;
                const int row = wm * 32 + i * 16 + h2 * 8 + g;
                #pragma unroll
                for (int j = 0; j < 8; j++) {
                    const float w0 = __expf(s[i][j][h2*2])   * inv[idx];
                    const float w1 = __expf(s[i][j][h2*2+1]) * inv[idx];
                    if (wout)
                        *(float2*)(wout + ((size_t)bh * TT + q0 + row) * TT
                                        + kt * 128 + wn * 64 + j * 8 + ctg * 2)
                            = make_float2(w0, w1);
                    u32 hi, lo;
                    split2(w0, w1, hi, lo);
                    sWh[row * 68 + wn * 32 + j * 4 + ctg] = hi;
                    sWl[row * 68 + wn * 32 + j * 4 + ctg] = lo;
                }
            }

        // V store (regs already in flight)
        #pragma unroll
        for (int j = 0; j < 8; j++) {
            const int sel = j >> 2;
            const int qq = t + (j & 3) * 256;
            const int r = qq >> 3, sg = qq & 7;
            *(uint4*)((sel ? sVl : sVh) + r * 36 + sg * 4) = pv[j];
        }
        __syncthreads();

        // AV: O += W @ V   (V via ldmatrix.trans from [key][dk])
        #pragma unroll
        for (int ch = 0; ch < 8; ch++) {
            u32 aw[2][2][4];
            #pragma unroll
            for (int i = 0; i < 2; i++) {
                const u32 ad = (u32)(wm * 32 + i * 16) * 272 + ch * 32 + lro68;
                ldsm4(aw[i][0], bWh + ad);
                ldsm4(aw[i][1], bWl + ad);
            }
            #pragma unroll
            for (int jp = 0; jp < 2; jp++) {
                u32 bvh[4], bvl[4];
                const u32 vd = (u32)(ch * 16) * 144 + (u32)(wn * 32 + jp * 16) * 2 + lro36;
                ldsm4t(bvh, bVh + vd);
                ldsm4t(bvl, bVl + vd);
                #pragma unroll
                for (int jj = 0; jj < 2; jj++) {
                    const int j = jp * 2 + jj;
                    // trans pairing: j0 -> (r0,r1), j1 -> (r2,r3)
                    const u32 b0h = bvh[jj * 2], b1h = bvh[jj * 2 + 1];
                    const u32 b0l = bvl[jj * 2], b1l = bvl[jj * 2 + 1];
                    #pragma unroll
                    for (int i = 0; i < 2; i++) {
                        mma16816(o[i][j], aw[i][0][0], aw[i][0][1], aw[i][0][2], aw[i][0][3], b0h, b1h);
                        mma16816(o[i][j], aw[i][0][0], aw[i][0][1], aw[i][0][2], aw[i][0][3], b0l, b1l);
                        mma16816(o[i][j], aw[i][1][0], aw[i][1][1], aw[i][1][2], aw[i][1][3], b0h, b1h);
                    }
                }
            }
        }
    }

    // epilogue: split O -> attn scratch [B,T,D]
    __nv_bfloat16* Oh = g_sh + 7 * SEG;
    __nv_bfloat16* Ol = g_sl + 7 * SEG;
    #pragma unroll
    for (int i = 0; i < 2; i++)
        #pragma unroll
        for (int h2 = 0; h2 < 2; h2++) {
            const int row = q0 + wm * 32 + i * 16 + h2 * 8 + g;
            #pragma unroll
            for (int j = 0; j < 4; j++) {
                const int col = head * 64 + wn * 32 + j * 8 + ctg * 2;
                u32 hi, lo;
                split2(o[i][j][h2*2], o[i][j][h2*2+1], hi, lo);
                const size_t e = ((size_t)bb * TT + row) * DD + col;
                *(u32*)(Oh + e) = hi;
                *(u32*)(Ol + e) = lo;
            }
        }
}

// ---------------------------------------------------------------------------
extern "C" void kernel_launch(void* const* d_in, const int* in_sizes, int n_in,
                              void* d_out, int out_size)
{
    const float* query = (const float*)d_in[0];
    const float* key_  = (const float*)d_in[1];
    const float* value = (const float*)d_in[2];
    const float* W_q   = (const float*)d_in[3];
    const float* W_k   = (const float*)d_in[4];
    const float* W_v   = (const float*)d_in[5];
    const float* W_o   = (const float*)d_in[6];

    split_inputs<<<dim3(1024, 7), 256>>>(query, key_, value, W_q, W_k, W_v, W_o);

    proj_mma<<<dim3(8, 32, 3), 256>>>(nullptr, 1);   // Q, K, V

    const size_t OUT_E = (size_t)BB * TT * DD;
    const size_t W_E   = (size_t)BB * HH * TT * (size_t)TT;
    float* wout = nullptr;
    if ((size_t)out_size >= OUT_E + W_E)
        wout = (float*)d_out + OUT_E;

    const int smem = 45056 * (int)sizeof(u32);       // 180224 B
    cudaFuncSetAttribute(attn_mma,
                         cudaFuncAttributeMaxDynamicSharedMemorySize, smem);
    attn_mma<<<dim3(TT / 128, BB * HH), 256, smem>>>(wout);

    proj_mma<<<dim3(8, 32, 1), 256>>>((float*)d_out, 0);   // O projection
}

// round 5
// speedup vs baseline: 5.2005x; 1.0767x over previous
#include <cuda_runtime.h>
#include <cuda_bf16.h>
#include <math.h>

typedef unsigned int u32;

#define BB 2
#define TT 2048
#define DD 1024
#define HH 16
#define DK 64

#define SEG  4194304          // B*T*D
#define WSEG 1048576          // D*D
// scratch layout (bf16 elements) in g_sh/g_sl:
//  0:qin  SEG:kin  2S:vin  3S:wq  3S+W:wk  3S+2W:wv  3S+3W:wo
//  4S:Q[B,H,T,DK]  5S:K  6S:V  7S:attn[B,T,D]
__device__ __align__(16) __nv_bfloat16 g_sh[8 * SEG];
__device__ __align__(16) __nv_bfloat16 g_sl[8 * SEG];

// ---------------------------------------------------------------------------
__device__ __forceinline__ void split2(float x0, float x1, u32 &h, u32 &l)
{
    __nv_bfloat162 hh = __floats2bfloat162_rn(x0, x1);
    float r0 = x0 - __bfloat162float(__low2bfloat16(hh));
    float r1 = x1 - __bfloat162float(__high2bfloat16(hh));
    __nv_bfloat162 ll = __floats2bfloat162_rn(r0, r1);
    h = *reinterpret_cast<u32*>(&hh);
    l = *reinterpret_cast<u32*>(&ll);
}

__device__ __forceinline__ void mma16816(float* c,
    u32 a0, u32 a1, u32 a2, u32 a3, u32 b0, u32 b1)
{
    asm volatile(
        "mma.sync.aligned.m16n8k16.row.col.f32.bf16.bf16.f32 "
        "{%0,%1,%2,%3},{%4,%5,%6,%7},{%8,%9},{%0,%1,%2,%3};"
        : "+f"(c[0]), "+f"(c[1]), "+f"(c[2]), "+f"(c[3])
        : "r"(a0), "r"(a1), "r"(a2), "r"(a3), "r"(b0), "r"(b1));
}

__device__ __forceinline__ void ldsm4(u32* r, u32 addr)
{
    asm volatile("ldmatrix.sync.aligned.m8n8.x4.shared.b16 {%0,%1,%2,%3}, [%4];"
        : "=r"(r[0]), "=r"(r[1]), "=r"(r[2]), "=r"(r[3]) : "r"(addr));
}
__device__ __forceinline__ void ldsm4t(u32* r, u32 addr)
{
    asm volatile("ldmatrix.sync.aligned.m8n8.x4.trans.shared.b16 {%0,%1,%2,%3}, [%4];"
        : "=r"(r[0]), "=r"(r[1]), "=r"(r[2]), "=r"(r[3]) : "r"(addr));
}

__device__ __forceinline__ void cpa(u32 dst, const void* src)
{
    asm volatile("cp.async.cg.shared.global [%0], [%1], 16;" :: "r"(dst), "l"(src));
}
__device__ __forceinline__ void cpc() { asm volatile("cp.async.commit_group;"); }
#define CPW(n) asm volatile("cp.async.wait_group %0;" :: "n"(n))

__device__ __forceinline__ float ex2(float x)
{
    float y;
    asm("ex2.approx.ftz.f32 %0, %1;" : "=f"(y) : "f"(x));
    return y;
}

// ---------------------------------------------------------------------------
// Split all 7 fp32 inputs into bf16 hi/lo scratch.
// ---------------------------------------------------------------------------
__global__ void split_inputs(const float* q, const float* k, const float* v,
                             const float* wq, const float* wk, const float* wv,
                             const float* wo)
{
    const float* srcs[7] = {q, k, v, wq, wk, wv, wo};
    const int offs[7] = {0, SEG, 2*SEG, 3*SEG, 3*SEG+WSEG, 3*SEG+2*WSEG, 3*SEG+3*WSEG};
    const int cnts[7] = {SEG, SEG, SEG, WSEG, WSEG, WSEG, WSEG};
    const int sid = blockIdx.y;
    const float* src = srcs[sid];
    const int off = offs[sid], cnt = cnts[sid];
    for (int idx = (blockIdx.x * 256 + threadIdx.x) * 4; idx < cnt;
         idx += gridDim.x * 1024) {
        float4 x = *(const float4*)(src + idx);
        u32 h0, l0, h1, l1;
        split2(x.x, x.y, h0, l0);
        split2(x.z, x.w, h1, l1);
        *(u32*)(g_sh + off + idx)     = h0;
        *(u32*)(g_sh + off + idx + 2) = h1;
        *(u32*)(g_sl + off + idx)     = l0;
        *(u32*)(g_sl + off + idx + 2) = l1;
    }
}

// ---------------------------------------------------------------------------
// Projection GEMM, split bf16, cp.async 2-stage pipeline, 1 sync per k-tile.
// CTA 128x128, k-tile 32, 8 warps (2m x 4n).
// smem (u32): stage s at s*10240: Ah(2560) Al Bh Bl.  Total 81920 B dynamic.
// ---------------------------------------------------------------------------
#define PJS 20

extern __shared__ u32 smdyn[];

__global__ void __launch_bounds__(256) proj_mma(float* __restrict__ fout, int qkv)
{
    const int z = qkv ? blockIdx.z : 3;
    const int aoff = (z == 3) ? 7 * SEG : z * SEG;
    const int woff = 3 * SEG + z * WSEG;
    const __nv_bfloat16* Agh = g_sh + aoff;
    const __nv_bfloat16* Agl = g_sl + aoff;
    const __nv_bfloat16* Bgh = g_sh + woff;
    const __nv_bfloat16* Bgl = g_sl + woff;

    const int t = threadIdx.x, lane = t & 31, wid = t >> 5;
    const int g = lane >> 2, ctg = lane & 3;
    const int wm = wid >> 2, wn = wid & 3;
    const int m0 = blockIdx.y * 128, n0 = blockIdx.x * 128;

    const u32 sb = (u32)__cvta_generic_to_shared(smdyn);
    const u32 lro = ((lane & 7) + ((lane >> 3) & 1) * 8) * 80 + (lane >> 4) * 16;

    // copy mapping: 512 uint4 per array, 2 per thread
    const int r0_ = t >> 2,          sg0 = t & 3;
    const int r1_ = (t + 256) >> 2,  sg1 = (t + 256) & 3;
    const u32 d0 = (u32)(r0_ * PJS + sg0 * 4) * 4;   // byte offset in array
    const u32 d1 = (u32)(r1_ * PJS + sg1 * 4) * 4;

    float c[4][4][4];
    #pragma unroll
    for (int i = 0; i < 4; i++)
        #pragma unroll
        for (int j = 0; j < 4; j++)
            #pragma unroll
            for (int r = 0; r < 4; r++) c[i][j][r] = 0.f;

    // issue k-tile copies into stage st
    auto issue = [&](int k0, int st) {
        const u32 stb = sb + (u32)st * 40960;
        cpa(stb         + d0, Agh + (size_t)(m0 + r0_) * 1024 + k0 + sg0 * 8);
        cpa(stb         + d1, Agh + (size_t)(m0 + r1_) * 1024 + k0 + sg1 * 8);
        cpa(stb + 10240 + d0, Agl + (size_t)(m0 + r0_) * 1024 + k0 + sg0 * 8);
        cpa(stb + 10240 + d1, Agl + (size_t)(m0 + r1_) * 1024 + k0 + sg1 * 8);
        cpa(stb + 20480 + d0, Bgh + (size_t)(n0 + r0_) * 1024 + k0 + sg0 * 8);
        cpa(stb + 20480 + d1, Bgh + (size_t)(n0 + r1_) * 1024 + k0 + sg1 * 8);
        cpa(stb + 30720 + d0, Bgl + (size_t)(n0 + r0_) * 1024 + k0 + sg0 * 8);
        cpa(stb + 30720 + d1, Bgl + (size_t)(n0 + r1_) * 1024 + k0 + sg1 * 8);
        cpc();
    };

    issue(0, 0);

    for (int kt = 0; kt < 32; kt++) {
        CPW(0);
        __syncthreads();
        if (kt < 31) issue((kt + 1) * 32, (kt + 1) & 1);

        const u32 stb = sb + (u32)(kt & 1) * 40960;
        const u32 bAh = stb, bAl = stb + 10240, bBh = stb + 20480, bBl = stb + 30720;

        #pragma unroll
        for (int ch = 0; ch < 2; ch++) {
            u32 a[4][2][4];
            #pragma unroll
            for (int i = 0; i < 4; i++) {
                const u32 ad = (u32)(wm * 64 + i * 16) * 80 + ch * 32 + lro;
                ldsm4(a[i][0], bAh + ad);
                ldsm4(a[i][1], bAl + ad);
            }
            u32 bh_[2][4], bl_[2][4];
            #pragma unroll
            for (int jp = 0; jp < 2; jp++) {
                const u32 bd = (u32)(wn * 32 + jp * 16) * 80 + ch * 32 + lro;
                ldsm4(bh_[jp], bBh + bd);
                ldsm4(bl_[jp], bBl + bd);
            }
            #pragma unroll
            for (int jp = 0; jp < 2; jp++)
                #pragma unroll
                for (int jj = 0; jj < 2; jj++) {
                    const int j = jp * 2 + jj;
                    const u32 b0h = bh_[jp][jj], b1h = bh_[jp][2 + jj];
                    const u32 b0l = bl_[jp][jj], b1l = bl_[jp][2 + jj];
                    #pragma unroll
                    for (int i = 0; i < 4; i++) {
                        mma16816(c[i][j], a[i][0][0], a[i][0][1], a[i][0][2], a[i][0][3], b0h, b1h);
                        mma16816(c[i][j], a[i][0][0], a[i][0][1], a[i][0][2], a[i][0][3], b0l, b1l);
                        mma16816(c[i][j], a[i][1][0], a[i][1][1], a[i][1][2], a[i][1][3], b0h, b1h);
                    }
                }
        }
        __syncthreads();
    }

    // epilogue
    const float scale = (z == 0) ? 0.125f * 1.4426950408889634f : 1.0f;
    if (z < 3) {
        __nv_bfloat16* Oh = g_sh + (4 + z) * SEG;
        __nv_bfloat16* Ol = g_sl + (4 + z) * SEG;
        #pragma unroll
        for (int i = 0; i < 4; i++)
            #pragma unroll
            for (int h2 = 0; h2 < 2; h2++) {
                const int m = m0 + wm * 64 + i * 16 + h2 * 8 + g;
                const int b = m >> 11, tq = m & 2047;
                #pragma unroll
                for (int j = 0; j < 4; j++) {
                    const int n = n0 + wn * 32 + j * 8 + ctg * 2;
                    const int h = n >> 6, dk = n & 63;
                    u32 hi, lo;
                    split2(c[i][j][h2*2] * scale, c[i][j][h2*2+1] * scale, hi, lo);
                    const size_t e = (((size_t)(b * HH + h) * TT + tq) << 6) + dk;
                    *(u32*)(Oh + e) = hi;
                    *(u32*)(Ol + e) = lo;
                }
            }
    } else {
        #pragma unroll
        for (int i = 0; i < 4; i++)
            #pragma unroll
            for (int h2 = 0; h2 < 2; h2++) {
                const int m = m0 + wm * 64 + i * 16 + h2 * 8 + g;
                #pragma unroll
                for (int j = 0; j < 4; j++) {
                    const int n = n0 + wn * 32 + j * 8 + ctg * 2;
                    *(float2*)(fout + (size_t)m * 1024 + n)
                        = make_float2(c[i][j][h2*2], c[i][j][h2*2+1]);
                }
            }
    }
}

// ---------------------------------------------------------------------------
// Fused attention.  CTA = 128 q-rows of one (b,h); 8 warps (4m x 2n).
// Pass A: hi-only 1-MMA S, cp.async double-buffered K-hi, 1 sync/iter.
// Pass B: 3-MMA S + AV; K(hi+lo) double-buffered, V overlapped, 2 syncs/iter.
// smem (u32): Qh 0 Ql 4608 Kh0 9216 Kl0 13824 Kh1 18432 Kl1 23040
//             Vh 27648 Vl 32256 Wh 36864(8704) Wl 45568 ; total 217088 B.
// ---------------------------------------------------------------------------
__global__ void __launch_bounds__(256) attn_mma(float* __restrict__ wout)
{
    __shared__ float stats[256];

    const int t = threadIdx.x, lane = t & 31, wid = t >> 5;
    const int g = lane >> 2, ctg = lane & 3;
    const int wm = wid >> 1, wn = wid & 1;
    const int bh = blockIdx.y;
    const int q0 = blockIdx.x * 128;
    const int head = bh & 15, bb = bh >> 4;

    const __nv_bfloat16* Qgh = g_sh + 4 * SEG + (size_t)bh * TT * DK;
    const __nv_bfloat16* Qgl = g_sl + 4 * SEG + (size_t)bh * TT * DK;
    const __nv_bfloat16* Kgh = g_sh + 5 * SEG + (size_t)bh * TT * DK;
    const __nv_bfloat16* Kgl = g_sl + 5 * SEG + (size_t)bh * TT * DK;
    const __nv_bfloat16* Vgh = g_sh + 6 * SEG + (size_t)bh * TT * DK;
    const __nv_bfloat16* Vgl = g_sl + 6 * SEG + (size_t)bh * TT * DK;

    const u32 sb = (u32)__cvta_generic_to_shared(smdyn);
    u32* sWh = smdyn + 36864;
    u32* sWl = smdyn + 45568;
    const u32 bQh = sb, bQl = sb + 18432;
    const u32 bVh = sb + 110592, bVl = sb + 129024;
    const u32 bWh = sb + 147456, bWl = sb + 182272;

    const u32 lro36 = ((lane & 7) + ((lane >> 3) & 1) * 8) * 144 + (lane >> 4) * 16;
    const u32 lro68 = ((lane & 7) + ((lane >> 3) & 1) * 8) * 272 + (lane >> 4) * 16;

    // per-thread copy mapping for a 128x64 bf16 tile: 1024 uint4, 4 per thread
    int cr[4], cs[4]; u32 cd[4];
    #pragma unroll
    for (int u = 0; u < 4; u++) {
        const int idx = t + u * 256;
        cr[u] = idx >> 3; cs[u] = idx & 7;
        cd[u] = (u32)(cr[u] * 36 + cs[u] * 4) * 4;     // byte offset in tile
    }

    // ---- load Q tile (hi+lo, one time) ----
    #pragma unroll
    for (int u = 0; u < 4; u++) {
        *(uint4*)(smdyn + cr[u] * 36 + cs[u] * 4) =
            *(const uint4*)(Qgh + (size_t)(q0 + cr[u]) * DK + cs[u] * 8);
        *(uint4*)(smdyn + 4608 + cr[u] * 36 + cs[u] * 4) =
            *(const uint4*)(Qgl + (size_t)(q0 + cr[u]) * DK + cs[u] * 8);
    }

    float l_[4] = {0.f, 0.f, 0.f, 0.f};

    // pass A K-hi stages: stage0 @ 36864B, stage1 @ 73728B
    auto issueKhi = [&](int kt, int st) {
        const u32 stb = sb + (st ? 73728u : 36864u);
        #pragma unroll
        for (int u = 0; u < 4; u++)
            cpa(stb + cd[u], Kgh + (size_t)(kt * 128 + cr[u]) * DK + cs[u] * 8);
        cpc();
    };

    issueKhi(0, 0);

    // ============================ pass A ============================
    for (int kt = 0; kt < 16; kt++) {
        CPW(0);
        __syncthreads();
        if (kt < 15) issueKhi(kt + 1, (kt + 1) & 1);

        const u32 bKh = sb + ((kt & 1) ? 73728u : 36864u);

        float s[2][8][4];
        #pragma unroll
        for (int i = 0; i < 2; i++)
            #pragma unroll
            for (int j = 0; j < 8; j++)
                #pragma unroll
                for (int r = 0; r < 4; r++) s[i][j][r] = 0.f;

        #pragma unroll
        for (int ch = 0; ch < 4; ch++) {
            u32 a[2][4];
            #pragma unroll
            for (int i = 0; i < 2; i++)
                ldsm4(a[i], bQh + (u32)(wm * 32 + i * 16) * 144 + ch * 32 + lro36);
            #pragma unroll
            for (int jp = 0; jp < 4; jp++) {
                u32 bfh[4];
                ldsm4(bfh, bKh + (u32)(wn * 64 + jp * 16) * 144 + ch * 32 + lro36);
                #pragma unroll
                for (int jj = 0; jj < 2; jj++) {
                    const int j = jp * 2 + jj;
                    #pragma unroll
                    for (int i = 0; i < 2; i++)
                        mma16816(s[i][j], a[i][0], a[i][1], a[i][2], a[i][3],
                                 bfh[jj], bfh[2 + jj]);
                }
            }
        }

        #pragma unroll
        for (int i = 0; i < 2; i++)
            #pragma unroll
            for (int h2 = 0; h2 < 2; h2++) {
                float sum = 0.f;
                #pragma unroll
                for (int j = 0; j < 8; j++)
                    sum += ex2(s[i][j][h2*2]) + ex2(s[i][j][h2*2+1]);
                sum += __shfl_xor_sync(0xffffffffu, sum, 1);
                sum += __shfl_xor_sync(0xffffffffu, sum, 2);
                l_[i * 2 + h2] += sum;
            }
    }

    // ---- merge wn halves ----
    __syncthreads();
    if (ctg == 0) {
        #pragma unroll
        for (int i = 0; i < 2; i++)
            #pragma unroll
            for (int h2 = 0; h2 < 2; h2++) {
                const int row = wm * 32 + i * 16 + h2 * 8 + g;
                stats[row * 2 + wn] = l_[i * 2 + h2];
            }
    }
    __syncthreads();
    float inv[4];
    #pragma unroll
    for (int i = 0; i < 2; i++)
        #pragma unroll
        for (int h2 = 0; h2 < 2; h2++) {
            const int row = wm * 32 + i * 16 + h2 * 8 + g;
            inv[i * 2 + h2] = 1.f / (stats[row * 2 + 0] + stats[row * 2 + 1]);
        }

    float o[2][4][4];
    #pragma unroll
    for (int i = 0; i < 2; i++)
        #pragma unroll
        for (int j = 0; j < 4; j++)
            #pragma unroll
            for (int r = 0; r < 4; r++) o[i][j][r] = 0.f;

    // pass B K stages (hi+lo)
    auto issueK = [&](int kt, int st) {
        const u32 sh_ = sb + (st ? 73728u : 36864u);
        #pragma unroll
        for (int u = 0; u < 4; u++) {
            cpa(sh_ + cd[u],          Kgh + (size_t)(kt * 128 + cr[u]) * DK + cs[u] * 8);
            cpa(sh_ + 18432u + cd[u], Kgl + (size_t)(kt * 128 + cr[u]) * DK + cs[u] * 8);
        }
        cpc();
    };
    auto issueV = [&](int kt) {
        #pragma unroll
        for (int u = 0; u < 4; u++) {
            cpa(bVh + cd[u], Vgh + (size_t)(kt * 128 + cr[u]) * DK + cs[u] * 8);
            cpa(bVl + cd[u], Vgl + (size_t)(kt * 128 + cr[u]) * DK + cs[u] * 8);
        }
        cpc();
    };

    issueK(0, 0);

    // ============================ pass B ============================
    for (int kt = 0; kt < 16; kt++) {
        CPW(0);
        __syncthreads();                    // K(kt) visible; AV(kt-1) done everywhere
        issueV(kt);
        if (kt < 15) issueK(kt + 1, (kt + 1) & 1);

        const u32 bKh = sb + ((kt & 1) ? 73728u : 36864u);
        const u32 bKl = bKh + 18432u;

        float s[2][8][4];
        #pragma unroll
        for (int i = 0; i < 2; i++)
            #pragma unroll
            for (int j = 0; j < 8; j++)
                #pragma unroll
                for (int r = 0; r < 4; r++) s[i][j][r] = 0.f;

        #pragma unroll
        for (int ch = 0; ch < 4; ch++) {
            u32 a[2][2][4];
            #pragma unroll
            for (int i = 0; i < 2; i++) {
                const u32 ad = (u32)(wm * 32 + i * 16) * 144 + ch * 32 + lro36;
                ldsm4(a[i][0], bQh + ad);
                ldsm4(a[i][1], bQl + ad);
            }
            #pragma unroll
            for (int jp = 0; jp < 4; jp++) {
                u32 bfh[4], bfl[4];
                const u32 bd = (u32)(wn * 64 + jp * 16) * 144 + ch * 32 + lro36;
                ldsm4(bfh, bKh + bd);
                ldsm4(bfl, bKl + bd);
                #pragma unroll
                for (int jj = 0; jj < 2; jj++) {
                    const int j = jp * 2 + jj;
                    const u32 b0h = bfh[jj], b1h = bfh[2 + jj];
                    const u32 b0l = bfl[jj], b1l = bfl[2 + jj];
                    #pragma unroll
                    for (int i = 0; i < 2; i++) {
                        mma16816(s[i][j], a[i][0][0], a[i][0][1], a[i][0][2], a[i][0][3], b0h, b1h);
                        mma16816(s[i][j], a[i][0][0], a[i][0][1], a[i][0][2], a[i][0][3], b0l, b1l);
                        mma16816(s[i][j], a[i][1][0], a[i][1][1], a[i][1][2], a[i][1][3], b0h, b1h);
                    }
                }
            }
        }

        // normalized weights: gmem + split into W smem
        #pragma unroll
        for (int i = 0; i < 2; i++)
            #pragma unroll
            for (int h2 = 0; h2 < 2; h2++) {
                const int idx = i * 2 + h2;
                const int row = wm * 32 + i * 16 + h2 * 8 + g;
                #pragma unroll
                for (int j = 0; j < 8; j++) {
                    const float w0 = ex2(s[i][j][h2*2])   * inv[idx];
                    const float w1 = ex2(s[i][j][h2*2+1]) * inv[idx];
                    if (wout)
                        *(float2*)(wout + ((size_t)bh * TT + q0 + row) * TT
                                        + kt * 128 + wn * 64 + j * 8 + ctg * 2)
                            = make_float2(w0, w1);
                    u32 hi, lo;
                    split2(w0, w1, hi, lo);
                    sWh[row * 68 + wn * 32 + j * 4 + ctg] = hi;
                    sWl[row * 68 + wn * 32 + j * 4 + ctg] = lo;
                }
            }

        if (kt < 15) { CPW(1); } else { CPW(0); }   // V done, next-K may pend
        __syncthreads();

        // AV: O += W @ V
        #pragma unroll
        for (int ch = 0; ch < 8; ch++) {
            u32 aw[2][2][4];
            #pragma unroll
            for (int i = 0; i < 2; i++) {
                const u32 ad = (u32)(wm * 32 + i * 16) * 272 + ch * 32 + lro68;
                ldsm4(aw[i][0], bWh + ad);
                ldsm4(aw[i][1], bWl + ad);
            }
            #pragma unroll
            for (int jp = 0; jp < 2; jp++) {
                u32 bvh[4], bvl[4];
                const u32 vd = (u32)(ch * 16) * 144 + (u32)(wn * 32 + jp * 16) * 2 + lro36;
                ldsm4t(bvh, bVh + vd);
                ldsm4t(bvl, bVl + vd);
                #pragma unroll
                for (int jj = 0; jj < 2; jj++) {
                    const int j = jp * 2 + jj;
                    const u32 b0h = bvh[jj * 2], b1h = bvh[jj * 2 + 1];
                    const u32 b0l = bvl[jj * 2], b1l = bvl[jj * 2 + 1];
                    #pragma unroll
                    for (int i = 0; i < 2; i++) {
                        mma16816(o[i][j], aw[i][0][0], aw[i][0][1], aw[i][0][2], aw[i][0][3], b0h, b1h);
                        mma16816(o[i][j], aw[i][0][0], aw[i][0][1], aw[i][0][2], aw[i][0][3], b0l, b1l);
                        mma16816(o[i][j], aw[i][1][0], aw[i][1][1], aw[i][1][2], aw[i][1][3], b0h, b1h);
                    }
                }
            }
        }
    }

    // epilogue: split O -> attn scratch [B,T,D]
    __nv_bfloat16* Oh = g_sh + 7 * SEG;
    __nv_bfloat16* Ol = g_sl + 7 * SEG;
    #pragma unroll
    for (int i = 0; i < 2; i++)
        #pragma unroll
        for (int h2 = 0; h2 < 2; h2++) {
            const int row = q0 + wm * 32 + i * 16 + h2 * 8 + g;
            #pragma unroll
            for (int j = 0; j < 4; j++) {
                const int col = head * 64 + wn * 32 + j * 8 + ctg * 2;
                u32 hi, lo;
                split2(o[i][j][h2*2], o[i][j][h2*2+1], hi, lo);
                const size_t e = ((size_t)bb * TT + row) * DD + col;
                *(u32*)(Oh + e) = hi;
                *(u32*)(Ol + e) = lo;
            }
        }
}

// ---------------------------------------------------------------------------
extern "C" void kernel_launch(void* const* d_in, const int* in_sizes, int n_in,
                              void* d_out, int out_size)
{
    const float* query = (const float*)d_in[0];
    const float* key_  = (const float*)d_in[1];
    const float* value = (const float*)d_in[2];
    const float* W_q   = (const float*)d_in[3];
    const float* W_k   = (const float*)d_in[4];
    const float* W_v   = (const float*)d_in[5];
    const float* W_o   = (const float*)d_in[6];

    split_inputs<<<dim3(1024, 7), 256>>>(query, key_, value, W_q, W_k, W_v, W_o);

    const int psmem = 81920;
    cudaFuncSetAttribute(proj_mma,
                         cudaFuncAttributeMaxDynamicSharedMemorySize, psmem);
    proj_mma<<<dim3(8, 32, 3), 256, psmem>>>(nullptr, 1);   // Q, K, V

    const size_t OUT_E = (size_t)BB * TT * DD;
    const size_t W_E   = (size_t)BB * HH * TT * (size_t)TT;
    float* wout = nullptr;
    if ((size_t)out_size >= OUT_E + W_E)
        wout = (float*)d_out + OUT_E;

    const int asmem = 54272 * (int)sizeof(u32);    // 217088 B
    cudaFuncSetAttribute(attn_mma,
                         cudaFuncAttributeMaxDynamicSharedMemorySize, asmem);
    attn_mma<<<dim3(TT / 128, BB * HH), 256, asmem>>>(wout);

    proj_mma<<<dim3(8, 32, 1), 256, psmem>>>((float*)d_out, 0);   // O projection
}

// round 7
// speedup vs baseline: 5.5020x; 1.0580x over previous
#include <cuda_runtime.h>
#include <cuda_bf16.h>
#include <math.h>

typedef unsigned int u32;

#define BB 2
#define TT 2048
#define DD 1024
#define HH 16
#define DK 64

#define SEG  4194304          // B*T*D
#define WSEG 1048576          // D*D
// scratch layout (bf16 elements) in g_sh/g_sl:
//  0:qin  SEG:kin  2S:vin  3S:wq  3S+W:wk  3S+2W:wv  3S+3W:wo
//  4S:Q[B,H,T,DK]  5S:K  6S:V  7S:attn[B,T,D]
__device__ __align__(16) __nv_bfloat16 g_sh[8 * SEG];
__device__ __align__(16) __nv_bfloat16 g_sl[8 * SEG];

// ---------------------------------------------------------------------------
__device__ __forceinline__ void split2(float x0, float x1, u32 &h, u32 &l)
{
    __nv_bfloat162 hh = __floats2bfloat162_rn(x0, x1);
    float r0 = x0 - __bfloat162float(__low2bfloat16(hh));
    float r1 = x1 - __bfloat162float(__high2bfloat16(hh));
    __nv_bfloat162 ll = __floats2bfloat162_rn(r0, r1);
    h = *reinterpret_cast<u32*>(&hh);
    l = *reinterpret_cast<u32*>(&ll);
}

__device__ __forceinline__ void mma16816(float* c,
    u32 a0, u32 a1, u32 a2, u32 a3, u32 b0, u32 b1)
{
    asm volatile(
        "mma.sync.aligned.m16n8k16.row.col.f32.bf16.bf16.f32 "
        "{%0,%1,%2,%3},{%4,%5,%6,%7},{%8,%9},{%0,%1,%2,%3};"
        : "+f"(c[0]), "+f"(c[1]), "+f"(c[2]), "+f"(c[3])
        : "r"(a0), "r"(a1), "r"(a2), "r"(a3), "r"(b0), "r"(b1));
}

__device__ __forceinline__ void ldsm4(u32* r, u32 addr)
{
    asm volatile("ldmatrix.sync.aligned.m8n8.x4.shared.b16 {%0,%1,%2,%3}, [%4];"
        : "=r"(r[0]), "=r"(r[1]), "=r"(r[2]), "=r"(r[3]) : "r"(addr));
}
__device__ __forceinline__ void ldsm4t(u32* r, u32 addr)
{
    asm volatile("ldmatrix.sync.aligned.m8n8.x4.trans.shared.b16 {%0,%1,%2,%3}, [%4];"
        : "=r"(r[0]), "=r"(r[1]), "=r"(r[2]), "=r"(r[3]) : "r"(addr));
}

__device__ __forceinline__ void cpa(u32 dst, const void* src)
{
    asm volatile("cp.async.cg.shared.global [%0], [%1], 16;" :: "r"(dst), "l"(src));
}
__device__ __forceinline__ void cpc() { asm volatile("cp.async.commit_group;"); }
#define CPW(n) asm volatile("cp.async.wait_group %0;" :: "n"(n))

__device__ __forceinline__ float ex2(float x)
{
    float y;
    asm("ex2.approx.ftz.f32 %0, %1;" : "=f"(y) : "f"(x));
    return y;
}

// ---------------------------------------------------------------------------
__global__ void split_inputs(const float* q, const float* k, const float* v,
                             const float* wq, const float* wk, const float* wv,
                             const float* wo)
{
    const float* srcs[7] = {q, k, v, wq, wk, wv, wo};
    const int offs[7] = {0, SEG, 2*SEG, 3*SEG, 3*SEG+WSEG, 3*SEG+2*WSEG, 3*SEG+3*WSEG};
    const int cnts[7] = {SEG, SEG, SEG, WSEG, WSEG, WSEG, WSEG};
    const int sid = blockIdx.y;
    const float* src = srcs[sid];
    const int off = offs[sid], cnt = cnts[sid];
    for (int idx = (blockIdx.x * 256 + threadIdx.x) * 4; idx < cnt;
         idx += gridDim.x * 1024) {
        float4 x = *(const float4*)(src + idx);
        u32 h0, l0, h1, l1;
        split2(x.x, x.y, h0, l0);
        split2(x.z, x.w, h1, l1);
        *(u32*)(g_sh + off + idx)     = h0;
        *(u32*)(g_sh + off + idx + 2) = h1;
        *(u32*)(g_sl + off + idx)     = l0;
        *(u32*)(g_sl + off + idx + 2) = l1;
    }
}

// ---------------------------------------------------------------------------
// Projection GEMM, split bf16, cp.async 2-stage, 512 threads (16 warps 4x4),
// warp tile 32x32.  CTA tile 128x128, k-tile 32.
// smem (u32): stage s at s*10240: Ah(2560) Al Bh Bl.  81920 B dynamic.
// ---------------------------------------------------------------------------
#define PJS 20

extern __shared__ u32 smdyn[];

__global__ void __launch_bounds__(512) proj_mma(float* __restrict__ fout, int qkv)
{
    const int z = qkv ? blockIdx.z : 3;
    const int aoff = (z == 3) ? 7 * SEG : z * SEG;
    const int woff = 3 * SEG + z * WSEG;
    const __nv_bfloat16* Agh = g_sh + aoff;
    const __nv_bfloat16* Agl = g_sl + aoff;
    const __nv_bfloat16* Bgh = g_sh + woff;
    const __nv_bfloat16* Bgl = g_sl + woff;

    const int t = threadIdx.x, lane = t & 31, wid = t >> 5;
    const int g = lane >> 2, ctg = lane & 3;
    const int wm = wid >> 2, wn = wid & 3;          // 4 x 4 warps
    const int m0 = blockIdx.y * 128, n0 = blockIdx.x * 128;

    const u32 sb = (u32)__cvta_generic_to_shared(smdyn);
    const u32 lro = ((lane & 7) + ((lane >> 3) & 1) * 8) * 80 + (lane >> 4) * 16;

    // copy mapping: 512 uint4 per array, 1 per thread
    const int r_ = t >> 2, sg_ = t & 3;
    const u32 d_ = (u32)(r_ * PJS + sg_ * 4) * 4;

    float c[2][4][4];
    #pragma unroll
    for (int i = 0; i < 2; i++)
        #pragma unroll
        for (int j = 0; j < 4; j++)
            #pragma unroll
            for (int r = 0; r < 4; r++) c[i][j][r] = 0.f;

    auto issue = [&](int k0, int st) {
        const u32 stb = sb + (u32)st * 40960;
        cpa(stb         + d_, Agh + (size_t)(m0 + r_) * 1024 + k0 + sg_ * 8);
        cpa(stb + 10240 + d_, Agl + (size_t)(m0 + r_) * 1024 + k0 + sg_ * 8);
        cpa(stb + 20480 + d_, Bgh + (size_t)(n0 + r_) * 1024 + k0 + sg_ * 8);
        cpa(stb + 30720 + d_, Bgl + (size_t)(n0 + r_) * 1024 + k0 + sg_ * 8);
        cpc();
    };

    issue(0, 0);

    for (int kt = 0; kt < 32; kt++) {
        CPW(0);
        __syncthreads();
        if (kt < 31) issue((kt + 1) * 32, (kt + 1) & 1);

        const u32 stb = sb + (u32)(kt & 1) * 40960;
        const u32 bAh = stb, bAl = stb + 10240, bBh = stb + 20480, bBl = stb + 30720;

        #pragma unroll
        for (int ch = 0; ch < 2; ch++) {
            u32 a[2][2][4];
            #pragma unroll
            for (int i = 0; i < 2; i++) {
                const u32 ad = (u32)(wm * 32 + i * 16) * 80 + ch * 32 + lro;
                ldsm4(a[i][0], bAh + ad);
                ldsm4(a[i][1], bAl + ad);
            }
            u32 bh_[2][4], bl_[2][4];
            #pragma unroll
            for (int jp = 0; jp < 2; jp++) {
                const u32 bd = (u32)(wn * 32 + jp * 16) * 80 + ch * 32 + lro;
                ldsm4(bh_[jp], bBh + bd);
                ldsm4(bl_[jp], bBl + bd);
            }
            #pragma unroll
            for (int jp = 0; jp < 2; jp++)
                #pragma unroll
                for (int jj = 0; jj < 2; jj++) {
                    const int j = jp * 2 + jj;
                    const u32 b0h = bh_[jp][jj], b1h = bh_[jp][2 + jj];
                    const u32 b0l = bl_[jp][jj], b1l = bl_[jp][2 + jj];
                    #pragma unroll
                    for (int i = 0; i < 2; i++) {
                        mma16816(c[i][j], a[i][0][0], a[i][0][1], a[i][0][2], a[i][0][3], b0h, b1h);
                        mma16816(c[i][j], a[i][0][0], a[i][0][1], a[i][0][2], a[i][0][3], b0l, b1l);
                        mma16816(c[i][j], a[i][1][0], a[i][1][1], a[i][1][2], a[i][1][3], b0h, b1h);
                    }
                }
        }
        __syncthreads();
    }

    // epilogue
    const float scale = (z == 0) ? 0.125f * 1.4426950408889634f : 1.0f;
    if (z < 3) {
        __nv_bfloat16* Oh = g_sh + (4 + z) * SEG;
        __nv_bfloat16* Ol = g_sl + (4 + z) * SEG;
        #pragma unroll
        for (int i = 0; i < 2; i++)
            #pragma unroll
            for (int h2 = 0; h2 < 2; h2++) {
                const int m = m0 + wm * 32 + i * 16 + h2 * 8 + g;
                const int b = m >> 11, tq = m & 2047;
                #pragma unroll
                for (int j = 0; j < 4; j++) {
                    const int n = n0 + wn * 32 + j * 8 + ctg * 2;
                    const int h = n >> 6, dk = n & 63;
                    u32 hi, lo;
                    split2(c[i][j][h2*2] * scale, c[i][j][h2*2+1] * scale, hi, lo);
                    const size_t e = (((size_t)(b * HH + h) * TT + tq) << 6) + dk;
                    *(u32*)(Oh + e) = hi;
                    *(u32*)(Ol + e) = lo;
                }
            }
    } else {
        #pragma unroll
        for (int i = 0; i < 2; i++)
            #pragma unroll
            for (int h2 = 0; h2 < 2; h2++) {
                const int m = m0 + wm * 32 + i * 16 + h2 * 8 + g;
                #pragma unroll
                for (int j = 0; j < 4; j++) {
                    const int n = n0 + wn * 32 + j * 8 + ctg * 2;
                    *(float2*)(fout + (size_t)m * 1024 + n)
                        = make_float2(c[i][j][h2*2], c[i][j][h2*2+1]);
                }
            }
    }
}

// ---------------------------------------------------------------------------
// Fused attention, 512 threads (16 warps).
// S phase: warp = 32 rows (wm) x 32 cols (wn); AV: 32 rows x 16 cols.
// Pass A: hi-only S; pass B: 3-MMA S + weights + 3-MMA AV.
// smem layout (bytes): Qh 0 Ql 18432 | K stages 36864 & 73728 (hi,lo 18432 ea)
//   Vh 110592 Vl 129024 | Wh 147456(34816) Wl 182272 ; total 217088 B.
// ---------------------------------------------------------------------------
__global__ void __launch_bounds__(512) attn_mma(float* __restrict__ wout)
{
    __shared__ float stats[512];

    const int t = threadIdx.x, lane = t & 31, wid = t >> 5;
    const int g = lane >> 2, ctg = lane & 3;
    const int wm = wid >> 2, wn = wid & 3;          // 4 x 4 warps
    const int bh = blockIdx.y;
    const int q0 = blockIdx.x * 128;
    const int head = bh & 15, bb = bh >> 4;

    const __nv_bfloat16* Qgh = g_sh + 4 * SEG + (size_t)bh * TT * DK;
    const __nv_bfloat16* Qgl = g_sl + 4 * SEG + (size_t)bh * TT * DK;
    const __nv_bfloat16* Kgh = g_sh + 5 * SEG + (size_t)bh * TT * DK;
    const __nv_bfloat16* Kgl = g_sl + 5 * SEG + (size_t)bh * TT * DK;
    const __nv_bfloat16* Vgh = g_sh + 6 * SEG + (size_t)bh * TT * DK;
    const __nv_bfloat16* Vgl = g_sl + 6 * SEG + (size_t)bh * TT * DK;

    const u32 sb = (u32)__cvta_generic_to_shared(smdyn);
    u32* sWh = smdyn + 36864;
    u32* sWl = smdyn + 45568;
    const u32 bQh = sb, bQl = sb + 18432;
    const u32 bVh = sb + 110592, bVl = sb + 129024;
    const u32 bWh = sb + 147456, bWl = sb + 182272;

    const u32 lro36 = ((lane & 7) + ((lane >> 3) & 1) * 8) * 144 + (lane >> 4) * 16;
    const u32 lro68 = ((lane & 7) + ((lane >> 3) & 1) * 8) * 272 + (lane >> 4) * 16;

    // copy mapping: 128x64 bf16 tile = 1024 uint4, 2 per thread
    int cr[2], cs[2]; u32 cd[2];
    #pragma unroll
    for (int u = 0; u < 2; u++) {
        const int idx = t + u * 512;
        cr[u] = idx >> 3; cs[u] = idx & 7;
        cd[u] = (u32)(cr[u] * 36 + cs[u] * 4) * 4;
    }

    // ---- load Q tile (hi+lo) ----
    #pragma unroll
    for (int u = 0; u < 2; u++) {
        *(uint4*)(smdyn + cr[u] * 36 + cs[u] * 4) =
            *(const uint4*)(Qgh + (size_t)(q0 + cr[u]) * DK + cs[u] * 8);
        *(uint4*)(smdyn + 4608 + cr[u] * 36 + cs[u] * 4) =
            *(const uint4*)(Qgl + (size_t)(q0 + cr[u]) * DK + cs[u] * 8);
    }

    float l_[4] = {0.f, 0.f, 0.f, 0.f};

    auto issueKhi = [&](int kt, int st) {
        const u32 stb = sb + (st ? 73728u : 36864u);
        #pragma unroll
        for (int u = 0; u < 2; u++)
            cpa(stb + cd[u], Kgh + (size_t)(kt * 128 + cr[u]) * DK + cs[u] * 8);
        cpc();
    };

    issueKhi(0, 0);

    // ============================ pass A ============================
    for (int kt = 0; kt < 16; kt++) {
        CPW(0);
        __syncthreads();
        if (kt < 15) issueKhi(kt + 1, (kt + 1) & 1);

        const u32 bKh = sb + ((kt & 1) ? 73728u : 36864u);

        float s[2][4][4];
        #pragma unroll
        for (int i = 0; i < 2; i++)
            #pragma unroll
            for (int j = 0; j < 4; j++)
                #pragma unroll
                for (int r = 0; r < 4; r++) s[i][j][r] = 0.f;

        #pragma unroll
        for (int ch = 0; ch < 4; ch++) {
            u32 a[2][4];
            #pragma unroll
            for (int i = 0; i < 2; i++)
                ldsm4(a[i], bQh + (u32)(wm * 32 + i * 16) * 144 + ch * 32 + lro36);
            #pragma unroll
            for (int jp = 0; jp < 2; jp++) {
                u32 bfh[4];
                ldsm4(bfh, bKh + (u32)(wn * 32 + jp * 16) * 144 + ch * 32 + lro36);
                #pragma unroll
                for (int jj = 0; jj < 2; jj++) {
                    const int j = jp * 2 + jj;
                    #pragma unroll
                    for (int i = 0; i < 2; i++)
                        mma16816(s[i][j], a[i][0], a[i][1], a[i][2], a[i][3],
                                 bfh[jj], bfh[2 + jj]);
                }
            }
        }

        #pragma unroll
        for (int i = 0; i < 2; i++)
            #pragma unroll
            for (int h2 = 0; h2 < 2; h2++) {
                float sum = 0.f;
                #pragma unroll
                for (int j = 0; j < 4; j++)
                    sum += ex2(s[i][j][h2*2]) + ex2(s[i][j][h2*2+1]);
                sum += __shfl_xor_sync(0xffffffffu, sum, 1);
                sum += __shfl_xor_sync(0xffffffffu, sum, 2);
                l_[i * 2 + h2] += sum;
            }
    }

    // ---- merge wn quarters ----
    __syncthreads();
    if (ctg == 0) {
        #pragma unroll
        for (int i = 0; i < 2; i++)
            #pragma unroll
            for (int h2 = 0; h2 < 2; h2++) {
                const int row = wm * 32 + i * 16 + h2 * 8 + g;
                stats[row * 4 + wn] = l_[i * 2 + h2];
            }
    }
    __syncthreads();
    float inv[4];
    #pragma unroll
    for (int i = 0; i < 2; i++)
        #pragma unroll
        for (int h2 = 0; h2 < 2; h2++) {
            const int row = wm * 32 + i * 16 + h2 * 8 + g;
            inv[i * 2 + h2] = 1.f / (stats[row * 4 + 0] + stats[row * 4 + 1]
                                   + stats[row * 4 + 2] + stats[row * 4 + 3]);
        }

    float o[2][2][4];
    #pragma unroll
    for (int i = 0; i < 2; i++)
        #pragma unroll
        for (int j = 0; j < 2; j++)
            #pragma unroll
            for (int r = 0; r < 4; r++) o[i][j][r] = 0.f;

    auto issueK = [&](int kt, int st) {
        const u32 sh_ = sb + (st ? 73728u : 36864u);
        #pragma unroll
        for (int u = 0; u < 2; u++) {
            cpa(sh_ + cd[u],          Kgh + (size_t)(kt * 128 + cr[u]) * DK + cs[u] * 8);
            cpa(sh_ + 18432u + cd[u], Kgl + (size_t)(kt * 128 + cr[u]) * DK + cs[u] * 8);
        }
        cpc();
    };
    auto issueV = [&](int kt) {
        #pragma unroll
        for (int u = 0; u < 2; u++) {
            cpa(bVh + cd[u], Vgh + (size_t)(kt * 128 + cr[u]) * DK + cs[u] * 8);
            cpa(bVl + cd[u], Vgl + (size_t)(kt * 128 + cr[u]) * DK + cs[u] * 8);
        }
        cpc();
    };

    issueK(0, 0);

    // ============================ pass B ============================
    for (int kt = 0; kt < 16; kt++) {
        CPW(0);
        __syncthreads();
        issueV(kt);
        if (kt < 15) issueK(kt + 1, (kt + 1) & 1);

        const u32 bKh = sb + ((kt & 1) ? 73728u : 36864u);
        const u32 bKl = bKh + 18432u;

        float s[2][4][4];
        #pragma unroll
        for (int i = 0; i < 2; i++)
            #pragma unroll
            for (int j = 0; j < 4; j++)
                #pragma unroll
                for (int r = 0; r < 4; r++) s[i][j][r] = 0.f;

        #pragma unroll
        for (int ch = 0; ch < 4; ch++) {
            u32 a[2][2][4];
            #pragma unroll
            for (int i = 0; i < 2; i++) {
                const u32 ad = (u32)(wm * 32 + i * 16) * 144 + ch * 32 + lro36;
                ldsm4(a[i][0], bQh + ad);
                ldsm4(a[i][1], bQl + ad);
            }
            #pragma unroll
            for (int jp = 0; jp < 2; jp++) {
                u32 bfh[4], bfl[4];
                const u32 bd = (u32)(wn * 32 + jp * 16) * 144 + ch * 32 + lro36;
                ldsm4(bfh, bKh + bd);
                ldsm4(bfl, bKl + bd);
                #pragma unroll
                for (int jj = 0; jj < 2; jj++) {
                    const int j = jp * 2 + jj;
                    const u32 b0h = bfh[jj], b1h = bfh[2 + jj];
                    const u32 b0l = bfl[jj], b1l = bfl[2 + jj];
                    #pragma unroll
                    for (int i = 0; i < 2; i++) {
                        mma16816(s[i][j], a[i][0][0], a[i][0][1], a[i][0][2], a[i][0][3], b0h, b1h);
                        mma16816(s[i][j], a[i][0][0], a[i][0][1], a[i][0][2], a[i][0][3], b0l, b1l);
                        mma16816(s[i][j], a[i][1][0], a[i][1][1], a[i][1][2], a[i][1][3], b0h, b1h);
                    }
                }
            }
        }

        // normalized weights -> gmem + split into W smem
        #pragma unroll
        for (int i = 0; i < 2; i++)
            #pragma unroll
            for (int h2 = 0; h2 < 2; h2++) {
                const int idx = i * 2 + h2;
                const int row = wm * 32 + i * 16 + h2 * 8 + g;
                #pragma unroll
                for (int j = 0; j < 4; j++) {
                    const float w0 = ex2(s[i][j][h2*2])   * inv[idx];
                    const float w1 = ex2(s[i][j][h2*2+1]) * inv[idx];
                    if (wout)
                        *(float2*)(wout + ((size_t)bh * TT + q0 + row) * TT
                                        + kt * 128 + wn * 32 + j * 8 + ctg * 2)
                            = make_float2(w0, w1);
                    u32 hi, lo;
                    split2(w0, w1, hi, lo);
                    sWh[row * 68 + wn * 16 + j * 4 + ctg] = hi;
                    sWl[row * 68 + wn * 16 + j * 4 + ctg] = lo;
                }
            }

        if (kt < 15) { CPW(1); } else { CPW(0); }
        __syncthreads();

        // AV: O += W @ V  (warp covers rows wm*32.., cols wn*16..)
        #pragma unroll
        for (int ch = 0; ch < 8; ch++) {
            u32 aw[2][2][4];
            #pragma unroll
            for (int i = 0; i < 2; i++) {
                const u32 ad = (u32)(wm * 32 + i * 16) * 272 + ch * 32 + lro68;
                ldsm4(aw[i][0], bWh + ad);
                ldsm4(aw[i][1], bWl + ad);
            }
            u32 bvh[4], bvl[4];
            const u32 vd = (u32)(ch * 16) * 144 + (u32)(wn * 16) * 2 + lro36;
            ldsm4t(bvh, bVh + vd);
            ldsm4t(bvl, bVl + vd);
            #pragma unroll
            for (int j = 0; j < 2; j++) {
                const u32 b0h = bvh[j * 2], b1h = bvh[j * 2 + 1];
                const u32 b0l = bvl[j * 2], b1l = bvl[j * 2 + 1];
                #pragma unroll
                for (int i = 0; i < 2; i++) {
                    mma16816(o[i][j], aw[i][0][0], aw[i][0][1], aw[i][0][2], aw[i][0][3], b0h, b1h);
                    mma16816(o[i][j], aw[i][0][0], aw[i][0][1], aw[i][0][2], aw[i][0][3], b0l, b1l);
                    mma16816(o[i][j], aw[i][1][0], aw[i][1][1], aw[i][1][2], aw[i][1][3], b0h, b1h);
                }
            }
        }
    }

    // epilogue: split O -> attn scratch [B,T,D]
    __nv_bfloat16* Oh = g_sh + 7 * SEG;
    __nv_bfloat16* Ol = g_sl + 7 * SEG;
    #pragma unroll
    for (int i = 0; i < 2; i++)
        #pragma unroll
        for (int h2 = 0; h2 < 2; h2++) {
            const int row = q0 + wm * 32 + i * 16 + h2 * 8 + g;
            #pragma unroll
            for (int j = 0; j < 2; j++) {
                const int col = head * 64 + wn * 16 + j * 8 + ctg * 2;
                u32 hi, lo;
                split2(o[i][j][h2*2], o[i][j][h2*2+1], hi, lo);
                const size_t e = ((size_t)bb * TT + row) * DD + col;
                *(u32*)(Oh + e) = hi;
                *(u32*)(Ol + e) = lo;
            }
        }
}

// ---------------------------------------------------------------------------
extern "C" void kernel_launch(void* const* d_in, const int* in_sizes, int n_in,
                              void* d_out, int out_size)
{
    const float* query = (const float*)d_in[0];
    const float* key_  = (const float*)d_in[1];
    const float* value = (const float*)d_in[2];
    const float* W_q   = (const float*)d_in[3];
    const float* W_k   = (const float*)d_in[4];
    const float* W_v   = (const float*)d_in[5];
    const float* W_o   = (const float*)d_in[6];

    split_inputs<<<dim3(1024, 7), 256>>>(query, key_, value, W_q, W_k, W_v, W_o);

    const int psmem = 81920;
    cudaFuncSetAttribute(proj_mma,
                         cudaFuncAttributeMaxDynamicSharedMemorySize, psmem);
    proj_mma<<<dim3(8, 32, 3), 512, psmem>>>(nullptr, 1);   // Q, K, V

    const size_t OUT_E = (size_t)BB * TT * DD;
    const size_t W_E   = (size_t)BB * HH * TT * (size_t)TT;
    float* wout = nullptr;
    if ((size_t)out_size >= OUT_E + W_E)
        wout = (float*)d_out + OUT_E;

    const int asmem = 54272 * (int)sizeof(u32);    // 217088 B
    cudaFuncSetAttribute(attn_mma,
                         cudaFuncAttributeMaxDynamicSharedMemorySize, asmem);
    attn_mma<<<dim3(TT / 128, BB * HH), 512, asmem>>>(wout);

    proj_mma<<<dim3(8, 32, 1), 512, psmem>>>((float*)d_out, 0);   // O projection
}

// round 9
// speedup vs baseline: 6.1129x; 1.1110x over previous
#include <cuda_runtime.h>
#include <cuda_fp16.h>
#include <math.h>

typedef unsigned int u32;

#define BB 2
#define TT 2048
#define DD 1024
#define HH 16
#define DK 64

#define SEG  4194304          // B*T*D
#define WSEG 1048576          // D*D
// scratch layout (fp16 elements) in g_sh/g_sl:
//  0:qin  SEG:kin  2S:vin  3S:wq  3S+W:wk  3S+2W:wv  3S+3W:wo
//  4S:Q[B,H,T,DK]  5S:K  6S:V  7S:attn[B,T,D]
__device__ __align__(16) __half g_sh[8 * SEG];
__device__ __align__(16) __half g_sl[8 * SEG];

// ---------------------------------------------------------------------------
// fp16 error-free-transform helpers
// ---------------------------------------------------------------------------
__device__ __forceinline__ void split2(float x0, float x1, u32 &h, u32 &l)
{
    __half2 hh = __floats2half2_rn(x0, x1);
    float r0 = x0 - __half2float(__low2half(hh));
    float r1 = x1 - __half2float(__high2half(hh));
    __half2 ll = __floats2half2_rn(r0, r1);
    h = *reinterpret_cast<u32*>(&hh);
    l = *reinterpret_cast<u32*>(&ll);
}

__device__ __forceinline__ void mma16816(float* c,
    u32 a0, u32 a1, u32 a2, u32 a3, u32 b0, u32 b1)
{
    asm volatile(
        "mma.sync.aligned.m16n8k16.row.col.f32.f16.f16.f32 "
        "{%0,%1,%2,%3},{%4,%5,%6,%7},{%8,%9},{%0,%1,%2,%3};"
        : "+f"(c[0]), "+f"(c[1]), "+f"(c[2]), "+f"(c[3])
        : "r"(a0), "r"(a1), "r"(a2), "r"(a3), "r"(b0), "r"(b1));
}

__device__ __forceinline__ void ldsm4(u32* r, u32 addr)
{
    asm volatile("ldmatrix.sync.aligned.m8n8.x4.shared.b16 {%0,%1,%2,%3}, [%4];"
        : "=r"(r[0]), "=r"(r[1]), "=r"(r[2]), "=r"(r[3]) : "r"(addr));
}
__device__ __forceinline__ void ldsm4t(u32* r, u32 addr)
{
    asm volatile("ldmatrix.sync.aligned.m8n8.x4.trans.shared.b16 {%0,%1,%2,%3}, [%4];"
        : "=r"(r[0]), "=r"(r[1]), "=r"(r[2]), "=r"(r[3]) : "r"(addr));
}

__device__ __forceinline__ void cpa(u32 dst, const void* src)
{
    asm volatile("cp.async.cg.shared.global [%0], [%1], 16;" :: "r"(dst), "l"(src));
}
__device__ __forceinline__ void cpc() { asm volatile("cp.async.commit_group;"); }
#define CPW(n) asm volatile("cp.async.wait_group %0;" :: "n"(n))

__device__ __forceinline__ float ex2(float x)
{
    float y;
    asm("ex2.approx.ftz.f32 %0, %1;" : "=f"(y) : "f"(x));
    return y;
}

// ---------------------------------------------------------------------------
__global__ void split_inputs(const float* q, const float* k, const float* v,
                             const float* wq, const float* wk, const float* wv,
                             const float* wo)
{
    const float* srcs[7] = {q, k, v, wq, wk, wv, wo};
    const int offs[7] = {0, SEG, 2*SEG, 3*SEG, 3*SEG+WSEG, 3*SEG+2*WSEG, 3*SEG+3*WSEG};
    const int cnts[7] = {SEG, SEG, SEG, WSEG, WSEG, WSEG, WSEG};
    const int sid = blockIdx.y;
    const float* src = srcs[sid];
    const int off = offs[sid], cnt = cnts[sid];
    for (int idx = (blockIdx.x * 256 + threadIdx.x) * 4; idx < cnt;
         idx += gridDim.x * 1024) {
        float4 x = *(const float4*)(src + idx);
        u32 h0, l0, h1, l1;
        split2(x.x, x.y, h0, l0);
        split2(x.z, x.w, h1, l1);
        *(u32*)(g_sh + off + idx)     = h0;
        *(u32*)(g_sh + off + idx + 2) = h1;
        *(u32*)(g_sl + off + idx)     = l0;
        *(u32*)(g_sl + off + idx + 2) = l1;
    }
}

// ---------------------------------------------------------------------------
// Projection GEMM, split fp16, cp.async 2-stage, 512 threads (16 warps 4x4),
// warp tile 32x32.  CTA tile 128x128, k-tile 32.  ONE sync per k-tile.
// smem (u32): stage s at s*10240: Ah(2560) Al Bh Bl.  81920 B dynamic.
// ---------------------------------------------------------------------------
#define PJS 20

extern __shared__ u32 smdyn[];

__global__ void __launch_bounds__(512) proj_mma(float* __restrict__ fout, int qkv)
{
    const int z = qkv ? blockIdx.z : 3;
    const int aoff = (z == 3) ? 7 * SEG : z * SEG;
    const int woff = 3 * SEG + z * WSEG;
    const __half* Agh = g_sh + aoff;
    const __half* Agl = g_sl + aoff;
    const __half* Bgh = g_sh + woff;
    const __half* Bgl = g_sl + woff;

    const int t = threadIdx.x, lane = t & 31, wid = t >> 5;
    const int g = lane >> 2, ctg = lane & 3;
    const int wm = wid >> 2, wn = wid & 3;          // 4 x 4 warps
    const int m0 = blockIdx.y * 128, n0 = blockIdx.x * 128;

    const u32 sb = (u32)__cvta_generic_to_shared(smdyn);
    const u32 lro = ((lane & 7) + ((lane >> 3) & 1) * 8) * 80 + (lane >> 4) * 16;

    const int r_ = t >> 2, sg_ = t & 3;
    const u32 d_ = (u32)(r_ * PJS + sg_ * 4) * 4;

    float c[2][4][4];
    #pragma unroll
    for (int i = 0; i < 2; i++)
        #pragma unroll
        for (int j = 0; j < 4; j++)
            #pragma unroll
            for (int r = 0; r < 4; r++) c[i][j][r] = 0.f;

    auto issue = [&](int k0, int st) {
        const u32 stb = sb + (u32)st * 40960;
        cpa(stb         + d_, Agh + (size_t)(m0 + r_) * 1024 + k0 + sg_ * 8);
        cpa(stb + 10240 + d_, Agl + (size_t)(m0 + r_) * 1024 + k0 + sg_ * 8);
        cpa(stb + 20480 + d_, Bgh + (size_t)(n0 + r_) * 1024 + k0 + sg_ * 8);
        cpa(stb + 30720 + d_, Bgl + (size_t)(n0 + r_) * 1024 + k0 + sg_ * 8);
        cpc();
    };

    issue(0, 0);

    for (int kt = 0; kt < 32; kt++) {
        CPW(0);
        __syncthreads();
        if (kt < 31) issue((kt + 1) * 32, (kt + 1) & 1);

        const u32 stb = sb + (u32)(kt & 1) * 40960;
        const u32 bAh = stb, bAl = stb + 10240, bBh = stb + 20480, bBl = stb + 30720;

        #pragma unroll
        for (int ch = 0; ch < 2; ch++) {
            u32 a[2][2][4];
            #pragma unroll
            for (int i = 0; i < 2; i++) {
                const u32 ad = (u32)(wm * 32 + i * 16) * 80 + ch * 32 + lro;
                ldsm4(a[i][0], bAh + ad);
                ldsm4(a[i][1], bAl + ad);
            }
            u32 bh_[2][4], bl_[2][4];
            #pragma unroll
            for (int jp = 0; jp < 2; jp++) {
                const u32 bd = (u32)(wn * 32 + jp * 16) * 80 + ch * 32 + lro;
                ldsm4(bh_[jp], bBh + bd);
                ldsm4(bl_[jp], bBl + bd);
            }
            #pragma unroll
            for (int jp = 0; jp < 2; jp++)
                #pragma unroll
                for (int jj = 0; jj < 2; jj++) {
                    const int j = jp * 2 + jj;
                    const u32 b0h = bh_[jp][jj], b1h = bh_[jp][2 + jj];
                    const u32 b0l = bl_[jp][jj], b1l = bl_[jp][2 + jj];
                    #pragma unroll
                    for (int i = 0; i < 2; i++) {
                        mma16816(c[i][j], a[i][0][0], a[i][0][1], a[i][0][2], a[i][0][3], b0h, b1h);
                        mma16816(c[i][j], a[i][0][0], a[i][0][1], a[i][0][2], a[i][0][3], b0l, b1l);
                        mma16816(c[i][j], a[i][1][0], a[i][1][1], a[i][1][2], a[i][1][3], b0h, b1h);
                    }
                }
        }
        // single sync per iter: the next iter's top sync orders compute vs the
        // following stage overwrite (stage touched next was read 2 iters ago).
    }

    // epilogue
    const float scale = (z == 0) ? 0.125f * 1.4426950408889634f : 1.0f;
    if (z < 3) {
        __half* Oh = g_sh + (4 + z) * SEG;
        __half* Ol = g_sl + (4 + z) * SEG;
        #pragma unroll
        for (int i = 0; i < 2; i++)
            #pragma unroll
            for (int h2 = 0; h2 < 2; h2++) {
                const int m = m0 + wm * 32 + i * 16 + h2 * 8 + g;
                const int b = m >> 11, tq = m & 2047;
                #pragma unroll
                for (int j = 0; j < 4; j++) {
                    const int n = n0 + wn * 32 + j * 8 + ctg * 2;
                    const int h = n >> 6, dk = n & 63;
                    u32 hi, lo;
                    split2(c[i][j][h2*2] * scale, c[i][j][h2*2+1] * scale, hi, lo);
                    const size_t e = (((size_t)(b * HH + h) * TT + tq) << 6) + dk;
                    *(u32*)(Oh + e) = hi;
                    *(u32*)(Ol + e) = lo;
                }
            }
    } else {
        #pragma unroll
        for (int i = 0; i < 2; i++)
            #pragma unroll
            for (int h2 = 0; h2 < 2; h2++) {
                const int m = m0 + wm * 32 + i * 16 + h2 * 8 + g;
                #pragma unroll
                for (int j = 0; j < 4; j++) {
                    const int n = n0 + wn * 32 + j * 8 + ctg * 2;
                    *(float2*)(fout + (size_t)m * 1024 + n)
                        = make_float2(c[i][j][h2*2], c[i][j][h2*2+1]);
                }
            }
    }
}

// ---------------------------------------------------------------------------
// Fused attention, 512 threads (16 warps), fp16 EFT.
// Pass A: hi-only 1-term S.  Pass B: 3-term S + weights + 1-term AV
// (W single fp16, V hi-only fp16).
// smem (bytes): Qh 0 Ql 18432 | K stages 36864 & 73728 (hi,lo 18432 ea)
//   Vh 110592 | Wh 147456(34816) ; alloc 217088 B (tail unused).
// ---------------------------------------------------------------------------
__global__ void __launch_bounds__(512) attn_mma(float* __restrict__ wout)
{
    __shared__ float stats[512];

    const int t = threadIdx.x, lane = t & 31, wid = t >> 5;
    const int g = lane >> 2, ctg = lane & 3;
    const int wm = wid >> 2, wn = wid & 3;          // 4 x 4 warps
    const int bh = blockIdx.y;
    const int q0 = blockIdx.x * 128;
    const int head = bh & 15, bb = bh >> 4;

    const __half* Qgh = g_sh + 4 * SEG + (size_t)bh * TT * DK;
    const __half* Qgl = g_sl + 4 * SEG + (size_t)bh * TT * DK;
    const __half* Kgh = g_sh + 5 * SEG + (size_t)bh * TT * DK;
    const __half* Kgl = g_sl + 5 * SEG + (size_t)bh * TT * DK;
    const __half* Vgh = g_sh + 6 * SEG + (size_t)bh * TT * DK;

    const u32 sb = (u32)__cvta_generic_to_shared(smdyn);
    u32* sWh = smdyn + 36864;                       // u32 index of Wh region
    const u32 bQh = sb, bQl = sb + 18432;
    const u32 bVh = sb + 110592;
    const u32 bWh = sb + 147456;

    const u32 lro36 = ((lane & 7) + ((lane >> 3) & 1) * 8) * 144 + (lane >> 4) * 16;
    const u32 lro68 = ((lane & 7) + ((lane >> 3) & 1) * 8) * 272 + (lane >> 4) * 16;

    // copy mapping: 128x64 fp16 tile = 1024 uint4, 2 per thread
    int cr[2], cs[2]; u32 cd[2];
    #pragma unroll
    for (int u = 0; u < 2; u++) {
        const int idx = t + u * 512;
        cr[u] = idx >> 3; cs[u] = idx & 7;
        cd[u] = (u32)(cr[u] * 36 + cs[u] * 4) * 4;
    }

    // ---- load Q tile (hi+lo) ----
    #pragma unroll
    for (int u = 0; u < 2; u++) {
        *(uint4*)(smdyn + cr[u] * 36 + cs[u] * 4) =
            *(const uint4*)(Qgh + (size_t)(q0 + cr[u]) * DK + cs[u] * 8);
        *(uint4*)(smdyn + 4608 + cr[u] * 36 + cs[u] * 4) =
            *(const uint4*)(Qgl + (size_t)(q0 + cr[u]) * DK + cs[u] * 8);
    }

    float l_[4] = {0.f, 0.f, 0.f, 0.f};

    auto issueKhi = [&](int kt, int st) {
        const u32 stb = sb + (st ? 73728u : 36864u);
        #pragma unroll
        for (int u = 0; u < 2; u++)
            cpa(stb + cd[u], Kgh + (size_t)(kt * 128 + cr[u]) * DK + cs[u] * 8);
        cpc();
    };

    issueKhi(0, 0);

    // ============================ pass A ============================
    for (int kt = 0; kt < 16; kt++) {
        CPW(0);
        __syncthreads();
        if (kt < 15) issueKhi(kt + 1, (kt + 1) & 1);

        const u32 bKh = sb + ((kt & 1) ? 73728u : 36864u);

        float s[2][4][4];
        #pragma unroll
        for (int i = 0; i < 2; i++)
            #pragma unroll
            for (int j = 0; j < 4; j++)
                #pragma unroll
                for (int r = 0; r < 4; r++) s[i][j][r] = 0.f;

        #pragma unroll
        for (int ch = 0; ch < 4; ch++) {
            u32 a[2][4];
            #pragma unroll
            for (int i = 0; i < 2; i++)
                ldsm4(a[i], bQh + (u32)(wm * 32 + i * 16) * 144 + ch * 32 + lro36);
            #pragma unroll
            for (int jp = 0; jp < 2; jp++) {
                u32 bfh[4];
                ldsm4(bfh, bKh + (u32)(wn * 32 + jp * 16) * 144 + ch * 32 + lro36);
                #pragma unroll
                for (int jj = 0; jj < 2; jj++) {
                    const int j = jp * 2 + jj;
                    #pragma unroll
                    for (int i = 0; i < 2; i++)
                        mma16816(s[i][j], a[i][0], a[i][1], a[i][2], a[i][3],
                                 bfh[jj], bfh[2 + jj]);
                }
            }
        }

        #pragma unroll
        for (int i = 0; i < 2; i++)
            #pragma unroll
            for (int h2 = 0; h2 < 2; h2++) {
                float sum = 0.f;
                #pragma unroll
                for (int j = 0; j < 4; j++)
                    sum += ex2(s[i][j][h2*2]) + ex2(s[i][j][h2*2+1]);
                sum += __shfl_xor_sync(0xffffffffu, sum, 1);
                sum += __shfl_xor_sync(0xffffffffu, sum, 2);
                l_[i * 2 + h2] += sum;
            }
    }

    // ---- merge wn quarters ----
    __syncthreads();
    if (ctg == 0) {
        #pragma unroll
        for (int i = 0; i < 2; i++)
            #pragma unroll
            for (int h2 = 0; h2 < 2; h2++) {
                const int row = wm * 32 + i * 16 + h2 * 8 + g;
                stats[row * 4 + wn] = l_[i * 2 + h2];
            }
    }
    __syncthreads();
    float inv[4];
    #pragma unroll
    for (int i = 0; i < 2; i++)
        #pragma unroll
        for (int h2 = 0; h2 < 2; h2++) {
            const int row = wm * 32 + i * 16 + h2 * 8 + g;
            inv[i * 2 + h2] = 1.f / (stats[row * 4 + 0] + stats[row * 4 + 1]
                                   + stats[row * 4 + 2] + stats[row * 4 + 3]);
        }

    float o[2][2][4];
    #pragma unroll
    for (int i = 0; i < 2; i++)
        #pragma unroll
        for (int j = 0; j < 2; j++)
            #pragma unroll
            for (int r = 0; r < 4; r++) o[i][j][r] = 0.f;

    auto issueK = [&](int kt, int st) {
        const u32 sh_ = sb + (st ? 73728u : 36864u);
        #pragma unroll
        for (int u = 0; u < 2; u++) {
            cpa(sh_ + cd[u],          Kgh + (size_t)(kt * 128 + cr[u]) * DK + cs[u] * 8);
            cpa(sh_ + 18432u + cd[u], Kgl + (size_t)(kt * 128 + cr[u]) * DK + cs[u] * 8);
        }
        cpc();
    };
    auto issueV = [&](int kt) {
        #pragma unroll
        for (int u = 0; u < 2; u++)
            cpa(bVh + cd[u], Vgh + (size_t)(kt * 128 + cr[u]) * DK + cs[u] * 8);
        cpc();
    };

    issueK(0, 0);

    // ============================ pass B ============================
    for (int kt = 0; kt < 16; kt++) {
        CPW(0);
        __syncthreads();
        issueV(kt);
        if (kt < 15) issueK(kt + 1, (kt + 1) & 1);

        const u32 bKh = sb + ((kt & 1) ? 73728u : 36864u);
        const u32 bKl = bKh + 18432u;

        float s[2][4][4];
        #pragma unroll
        for (int i = 0; i < 2; i++)
            #pragma unroll
            for (int j = 0; j < 4; j++)
                #pragma unroll
                for (int r = 0; r < 4; r++) s[i][j][r] = 0.f;

        #pragma unroll
        for (int ch = 0; ch < 4; ch++) {
            u32 a[2][2][4];
            #pragma unroll
            for (int i = 0; i < 2; i++) {
                const u32 ad = (u32)(wm * 32 + i * 16) * 144 + ch * 32 + lro36;
                ldsm4(a[i][0], bQh + ad);
                ldsm4(a[i][1], bQl + ad);
            }
            #pragma unroll
            for (int jp = 0; jp < 2; jp++) {
                u32 bfh[4], bfl[4];
                const u32 bd = (u32)(wn * 32 + jp * 16) * 144 + ch * 32 + lro36;
                ldsm4(bfh, bKh + bd);
                ldsm4(bfl, bKl + bd);
                #pragma unroll
                for (int jj = 0; jj < 2; jj++) {
                    const int j = jp * 2 + jj;
                    const u32 b0h = bfh[jj], b1h = bfh[2 + jj];
                    const u32 b0l = bfl[jj], b1l = bfl[2 + jj];
                    #pragma unroll
                    for (int i = 0; i < 2; i++) {
                        mma16816(s[i][j], a[i][0][0], a[i][0][1], a[i][0][2], a[i][0][3], b0h, b1h);
                        mma16816(s[i][j], a[i][0][0], a[i][0][1], a[i][0][2], a[i][0][3], b0l, b1l);
                        mma16816(s[i][j], a[i][1][0], a[i][1][1], a[i][1][2], a[i][1][3], b0h, b1h);
                    }
                }
            }
        }

        // normalized weights -> gmem + single-fp16 W into smem
        #pragma unroll
        for (int i = 0; i < 2; i++)
            #pragma unroll
            for (int h2 = 0; h2 < 2; h2++) {
                const int idx = i * 2 + h2;
                const int row = wm * 32 + i * 16 + h2 * 8 + g;
                #pragma unroll
                for (int j = 0; j < 4; j++) {
                    const float w0 = ex2(s[i][j][h2*2])   * inv[idx];
                    const float w1 = ex2(s[i][j][h2*2+1]) * inv[idx];
                    if (wout)
                        *(float2*)(wout + ((size_t)bh * TT + q0 + row) * TT
                                        + kt * 128 + wn * 32 + j * 8 + ctg * 2)
                            = make_float2(w0, w1);
                    __half2 wh2 = __floats2half2_rn(w0, w1);
                    sWh[row * 68 + wn * 16 + j * 4 + ctg] = *(u32*)&wh2;
                }
            }

        if (kt < 15) { CPW(1); } else { CPW(0); }
        __syncthreads();

        // AV: O += W @ V   (single term: Wh x Vh)
        #pragma unroll
        for (int ch = 0; ch < 8; ch++) {
            u32 aw[2][4];
            #pragma unroll
            for (int i = 0; i < 2; i++)
                ldsm4(aw[i], bWh + (u32)(wm * 32 + i * 16) * 272 + ch * 32 + lro68);
            u32 bvh[4];
            const u32 vd = (u32)(ch * 16) * 144 + (u32)(wn * 16) * 2 + lro36;
            ldsm4t(bvh, bVh + vd);
            #pragma unroll
            for (int j = 0; j < 2; j++) {
                #pragma unroll
                for (int i = 0; i < 2; i++)
                    mma16816(o[i][j], aw[i][0], aw[i][1], aw[i][2], aw[i][3],
                             bvh[j * 2], bvh[j * 2 + 1]);
            }
        }
    }

    // epilogue: split O -> attn scratch [B,T,D]
    __half* Oh = g_sh + 7 * SEG;
    __half* Ol = g_sl + 7 * SEG;
    #pragma unroll
    for (int i = 0; i < 2; i++)
        #pragma unroll
        for (int h2 = 0; h2 < 2; h2++) {
            const int row = q0 + wm * 32 + i * 16 + h2 * 8 + g;
            #pragma unroll
            for (int j = 0; j < 2; j++) {
                const int col = head * 64 + wn * 16 + j * 8 + ctg * 2;
                u32 hi, lo;
                split2(o[i][j][h2*2], o[i][j][h2*2+1], hi, lo);
                const size_t e = ((size_t)bb * TT + row) * DD + col;
                *(u32*)(Oh + e) = hi;
                *(u32*)(Ol + e) = lo;
            }
        }
}

// ---------------------------------------------------------------------------
extern "C" void kernel_launch(void* const* d_in, const int* in_sizes, int n_in,
                              void* d_out, int out_size)
{
    const float* query = (const float*)d_in[0];
    const float* key_  = (const float*)d_in[1];
    const float* value = (const float*)d_in[2];
    const float* W_q   = (const float*)d_in[3];
    const float* W_k   = (const float*)d_in[4];
    const float* W_v   = (const float*)d_in[5];
    const float* W_o   = (const float*)d_in[6];

    split_inputs<<<dim3(1024, 7), 256>>>(query, key_, value, W_q, W_k, W_v, W_o);

    const int psmem = 81920;
    cudaFuncSetAttribute(proj_mma,
                         cudaFuncAttributeMaxDynamicSharedMemorySize, psmem);
    proj_mma<<<dim3(8, 32, 3), 512, psmem>>>(nullptr, 1);   // Q, K, V

    const size_t OUT_E = (size_t)BB * TT * DD;
    const size_t W_E   = (size_t)BB * HH * TT * (size_t)TT;
    float* wout = nullptr;
    if ((size_t)out_size >= OUT_E + W_E)
        wout = (float*)d_out + OUT_E;

    const int asmem = 54272 * (int)sizeof(u32);    // 217088 B
    cudaFuncSetAttribute(attn_mma,
                         cudaFuncAttributeMaxDynamicSharedMemorySize, asmem);
    attn_mma<<<dim3(TT / 128, BB * HH), 512, asmem>>>(wout);

    proj_mma<<<dim3(8, 32, 1), 512, psmem>>>((float*)d_out, 0);   // O projection
}

// round 10
// speedup vs baseline: 7.5946x; 1.2424x over previous
#include <cuda_runtime.h>
#include <cuda_fp16.h>
#include <math.h>

typedef unsigned int u32;

#define BB 2
#define TT 2048
#define DD 1024
#define HH 16
#define DK 64

#define SEG  4194304          // B*T*D
#define WSEG 1048576          // D*D
// scratch layout (fp16 elements) in g_sh/g_sl:
//  0:qin  SEG:kin  2S:vin  3S:wq  3S+W:wk  3S+2W:wv  3S+3W:wo
//  4S:Q[B,H,T,DK]  5S:K  6S:V  7S:attn[B,T,D]
__device__ __align__(16) __half g_sh[8 * SEG];
__device__ __align__(16) __half g_sl[8 * SEG];

// ---------------------------------------------------------------------------
__device__ __forceinline__ void split2(float x0, float x1, u32 &h, u32 &l)
{
    __half2 hh = __floats2half2_rn(x0, x1);
    float r0 = x0 - __half2float(__low2half(hh));
    float r1 = x1 - __half2float(__high2half(hh));
    __half2 ll = __floats2half2_rn(r0, r1);
    h = *reinterpret_cast<u32*>(&hh);
    l = *reinterpret_cast<u32*>(&ll);
}

__device__ __forceinline__ void mma16816(float* c,
    u32 a0, u32 a1, u32 a2, u32 a3, u32 b0, u32 b1)
{
    asm volatile(
        "mma.sync.aligned.m16n8k16.row.col.f32.f16.f16.f32 "
        "{%0,%1,%2,%3},{%4,%5,%6,%7},{%8,%9},{%0,%1,%2,%3};"
        : "+f"(c[0]), "+f"(c[1]), "+f"(c[2]), "+f"(c[3])
        : "r"(a0), "r"(a1), "r"(a2), "r"(a3), "r"(b0), "r"(b1));
}

__device__ __forceinline__ void ldsm4(u32* r, u32 addr)
{
    asm volatile("ldmatrix.sync.aligned.m8n8.x4.shared.b16 {%0,%1,%2,%3}, [%4];"
        : "=r"(r[0]), "=r"(r[1]), "=r"(r[2]), "=r"(r[3]) : "r"(addr));
}
__device__ __forceinline__ void ldsm4t(u32* r, u32 addr)
{
    asm volatile("ldmatrix.sync.aligned.m8n8.x4.trans.shared.b16 {%0,%1,%2,%3}, [%4];"
        : "=r"(r[0]), "=r"(r[1]), "=r"(r[2]), "=r"(r[3]) : "r"(addr));
}

__device__ __forceinline__ void cpa(u32 dst, const void* src)
{
    asm volatile("cp.async.cg.shared.global [%0], [%1], 16;" :: "r"(dst), "l"(src));
}
__device__ __forceinline__ void cpc() { asm volatile("cp.async.commit_group;"); }
#define CPW(n) asm volatile("cp.async.wait_group %0;" :: "n"(n))

__device__ __forceinline__ float ex2(float x)
{
    float y;
    asm("ex2.approx.ftz.f32 %0, %1;" : "=f"(y) : "f"(x));
    return y;
}

// ---------------------------------------------------------------------------
__global__ void split_inputs(const float* q, const float* k, const float* v,
                             const float* wq, const float* wk, const float* wv,
                             const float* wo)
{
    const float* srcs[7] = {q, k, v, wq, wk, wv, wo};
    const int offs[7] = {0, SEG, 2*SEG, 3*SEG, 3*SEG+WSEG, 3*SEG+2*WSEG, 3*SEG+3*WSEG};
    const int cnts[7] = {SEG, SEG, SEG, WSEG, WSEG, WSEG, WSEG};
    const int sid = blockIdx.y;
    const float* src = srcs[sid];
    const int off = offs[sid], cnt = cnts[sid];
    for (int idx = (blockIdx.x * 256 + threadIdx.x) * 4; idx < cnt;
         idx += gridDim.x * 1024) {
        float4 x = *(const float4*)(src + idx);
        u32 h0, l0, h1, l1;
        split2(x.x, x.y, h0, l0);
        split2(x.z, x.w, h1, l1);
        *(u32*)(g_sh + off + idx)     = h0;
        *(u32*)(g_sh + off + idx + 2) = h1;
        *(u32*)(g_sl + off + idx)     = l0;
        *(u32*)(g_sl + off + idx + 2) = l1;
    }
}

// ---------------------------------------------------------------------------
// Projection GEMM, 2-term fp16 EFT: C = (Ah + Al) @ Wh^T.
// cp.async 2-stage, 512 threads (16 warps 4x4), warp tile 32x32.
// CTA tile 128x128, k-tile 32.  smem stage: Ah(10240B) Al Bh; stride 30720 B.
// ---------------------------------------------------------------------------
#define PJS 20

extern __shared__ u32 smdyn[];

__global__ void __launch_bounds__(512) proj_mma(float* __restrict__ fout, int qkv)
{
    const int z = qkv ? blockIdx.z : 3;
    const int aoff = (z == 3) ? 7 * SEG : z * SEG;
    const int woff = 3 * SEG + z * WSEG;
    const __half* Agh = g_sh + aoff;
    const __half* Agl = g_sl + aoff;
    const __half* Bgh = g_sh + woff;

    const int t = threadIdx.x, lane = t & 31, wid = t >> 5;
    const int g = lane >> 2, ctg = lane & 3;
    const int wm = wid >> 2, wn = wid & 3;          // 4 x 4 warps
    const int m0 = blockIdx.y * 128, n0 = blockIdx.x * 128;

    const u32 sb = (u32)__cvta_generic_to_shared(smdyn);
    const u32 lro = ((lane & 7) + ((lane >> 3) & 1) * 8) * 80 + (lane >> 4) * 16;

    const int r_ = t >> 2, sg_ = t & 3;
    const u32 d_ = (u32)(r_ * PJS + sg_ * 4) * 4;

    float c[2][4][4];
    #pragma unroll
    for (int i = 0; i < 2; i++)
        #pragma unroll
        for (int j = 0; j < 4; j++)
            #pragma unroll
            for (int r = 0; r < 4; r++) c[i][j][r] = 0.f;

    auto issue = [&](int k0, int st) {
        const u32 stb = sb + (u32)st * 30720;
        cpa(stb         + d_, Agh + (size_t)(m0 + r_) * 1024 + k0 + sg_ * 8);
        cpa(stb + 10240 + d_, Agl + (size_t)(m0 + r_) * 1024 + k0 + sg_ * 8);
        cpa(stb + 20480 + d_, Bgh + (size_t)(n0 + r_) * 1024 + k0 + sg_ * 8);
        cpc();
    };

    issue(0, 0);

    for (int kt = 0; kt < 32; kt++) {
        CPW(0);
        __syncthreads();
        if (kt < 31) issue((kt + 1) * 32, (kt + 1) & 1);

        const u32 stb = sb + (u32)(kt & 1) * 30720;
        const u32 bAh = stb, bAl = stb + 10240, bBh = stb + 20480;

        #pragma unroll
        for (int ch = 0; ch < 2; ch++) {
            u32 a[2][2][4];
            #pragma unroll
            for (int i = 0; i < 2; i++) {
                const u32 ad = (u32)(wm * 32 + i * 16) * 80 + ch * 32 + lro;
                ldsm4(a[i][0], bAh + ad);
                ldsm4(a[i][1], bAl + ad);
            }
            u32 bh_[2][4];
            #pragma unroll
            for (int jp = 0; jp < 2; jp++)
                ldsm4(bh_[jp], bBh + (u32)(wn * 32 + jp * 16) * 80 + ch * 32 + lro);
            #pragma unroll
            for (int jp = 0; jp < 2; jp++)
                #pragma unroll
                for (int jj = 0; jj < 2; jj++) {
                    const int j = jp * 2 + jj;
                    const u32 b0h = bh_[jp][jj], b1h = bh_[jp][2 + jj];
                    #pragma unroll
                    for (int i = 0; i < 2; i++) {
                        mma16816(c[i][j], a[i][0][0], a[i][0][1], a[i][0][2], a[i][0][3], b0h, b1h);
                        mma16816(c[i][j], a[i][1][0], a[i][1][1], a[i][1][2], a[i][1][3], b0h, b1h);
                    }
                }
        }
    }

    // epilogue
    const float scale = (z == 0) ? 0.125f * 1.4426950408889634f : 1.0f;
    if (z < 3) {
        __half* Oh = g_sh + (4 + z) * SEG;
        __half* Ol = g_sl + (4 + z) * SEG;
        #pragma unroll
        for (int i = 0; i < 2; i++)
            #pragma unroll
            for (int h2 = 0; h2 < 2; h2++) {
                const int m = m0 + wm * 32 + i * 16 + h2 * 8 + g;
                const int b = m >> 11, tq = m & 2047;
                #pragma unroll
                for (int j = 0; j < 4; j++) {
                    const int n = n0 + wn * 32 + j * 8 + ctg * 2;
                    const int h = n >> 6, dk = n & 63;
                    u32 hi, lo;
                    split2(c[i][j][h2*2] * scale, c[i][j][h2*2+1] * scale, hi, lo);
                    const size_t e = (((size_t)(b * HH + h) * TT + tq) << 6) + dk;
                    *(u32*)(Oh + e) = hi;
                    *(u32*)(Ol + e) = lo;
                }
            }
    } else {
        #pragma unroll
        for (int i = 0; i < 2; i++)
            #pragma unroll
            for (int h2 = 0; h2 < 2; h2++) {
                const int m = m0 + wm * 32 + i * 16 + h2 * 8 + g;
                #pragma unroll
                for (int j = 0; j < 4; j++) {
                    const int n = n0 + wn * 32 + j * 8 + ctg * 2;
                    *(float2*)(fout + (size_t)m * 1024 + n)
                        = make_float2(c[i][j][h2*2], c[i][j][h2*2+1]);
                }
            }
    }
}

// ---------------------------------------------------------------------------
// Fused attention, 512 threads (16 warps), fp16.
// Pass A: 1-term S (Qh x Kh).  Pass B: 2-term S ((Qh+Ql) x Kh) + weights +
// 1-term AV (W fp16 x Vh).  K-lo never touched.
// smem (bytes): Qh 0  Ql 18432 | K st0 36864  st1 55296 (hi only)
//   Vh 73728 | Wh 92160 (34816) ; total 126976 B.
// ---------------------------------------------------------------------------
__global__ void __launch_bounds__(512) attn_mma(float* __restrict__ wout)
{
    __shared__ float stats[512];

    const int t = threadIdx.x, lane = t & 31, wid = t >> 5;
    const int g = lane >> 2, ctg = lane & 3;
    const int wm = wid >> 2, wn = wid & 3;          // 4 x 4 warps
    const int bh = blockIdx.y;
    const int q0 = blockIdx.x * 128;
    const int head = bh & 15, bb = bh >> 4;

    const __half* Qgh = g_sh + 4 * SEG + (size_t)bh * TT * DK;
    const __half* Qgl = g_sl + 4 * SEG + (size_t)bh * TT * DK;
    const __half* Kgh = g_sh + 5 * SEG + (size_t)bh * TT * DK;
    const __half* Vgh = g_sh + 6 * SEG + (size_t)bh * TT * DK;

    const u32 sb = (u32)__cvta_generic_to_shared(smdyn);
    u32* sWh = smdyn + 23040;                       // u32 index of Wh region
    const u32 bQh = sb, bQl = sb + 18432;
    const u32 bVh = sb + 73728;
    const u32 bWh = sb + 92160;

    const u32 lro36 = ((lane & 7) + ((lane >> 3) & 1) * 8) * 144 + (lane >> 4) * 16;
    const u32 lro68 = ((lane & 7) + ((lane >> 3) & 1) * 8) * 272 + (lane >> 4) * 16;

    // copy mapping: 128x64 fp16 tile = 1024 uint4, 2 per thread
    int cr[2], cs[2]; u32 cd[2];
    #pragma unroll
    for (int u = 0; u < 2; u++) {
        const int idx = t + u * 512;
        cr[u] = idx >> 3; cs[u] = idx & 7;
        cd[u] = (u32)(cr[u] * 36 + cs[u] * 4) * 4;
    }

    // ---- load Q tile (hi+lo) ----
    #pragma unroll
    for (int u = 0; u < 2; u++) {
        *(uint4*)(smdyn + cr[u] * 36 + cs[u] * 4) =
            *(const uint4*)(Qgh + (size_t)(q0 + cr[u]) * DK + cs[u] * 8);
        *(uint4*)(smdyn + 4608 + cr[u] * 36 + cs[u] * 4) =
            *(const uint4*)(Qgl + (size_t)(q0 + cr[u]) * DK + cs[u] * 8);
    }

    float l_[4] = {0.f, 0.f, 0.f, 0.f};

    auto issueK = [&](int kt, int st) {
        const u32 stb = sb + 36864u + (u32)st * 18432u;
        #pragma unroll
        for (int u = 0; u < 2; u++)
            cpa(stb + cd[u], Kgh + (size_t)(kt * 128 + cr[u]) * DK + cs[u] * 8);
        cpc();
    };

    issueK(0, 0);

    // ============================ pass A ============================
    for (int kt = 0; kt < 16; kt++) {
        CPW(0);
        __syncthreads();
        if (kt < 15) issueK(kt + 1, (kt + 1) & 1);

        const u32 bKh = sb + 36864u + (u32)(kt & 1) * 18432u;

        float s[2][4][4];
        #pragma unroll
        for (int i = 0; i < 2; i++)
            #pragma unroll
            for (int j = 0; j < 4; j++)
                #pragma unroll
                for (int r = 0; r < 4; r++) s[i][j][r] = 0.f;

        #pragma unroll
        for (int ch = 0; ch < 4; ch++) {
            u32 a[2][4];
            #pragma unroll
            for (int i = 0; i < 2; i++)
                ldsm4(a[i], bQh + (u32)(wm * 32 + i * 16) * 144 + ch * 32 + lro36);
            #pragma unroll
            for (int jp = 0; jp < 2; jp++) {
                u32 bfh[4];
                ldsm4(bfh, bKh + (u32)(wn * 32 + jp * 16) * 144 + ch * 32 + lro36);
                #pragma unroll
                for (int jj = 0; jj < 2; jj++) {
                    const int j = jp * 2 + jj;
                    #pragma unroll
                    for (int i = 0; i < 2; i++)
                        mma16816(s[i][j], a[i][0], a[i][1], a[i][2], a[i][3],
                                 bfh[jj], bfh[2 + jj]);
                }
            }
        }

        #pragma unroll
        for (int i = 0; i < 2; i++)
            #pragma unroll
            for (int h2 = 0; h2 < 2; h2++) {
                float sum = 0.f;
                #pragma unroll
                for (int j = 0; j < 4; j++)
                    sum += ex2(s[i][j][h2*2]) + ex2(s[i][j][h2*2+1]);
                sum += __shfl_xor_sync(0xffffffffu, sum, 1);
                sum += __shfl_xor_sync(0xffffffffu, sum, 2);
                l_[i * 2 + h2] += sum;
            }
    }

    // ---- merge wn quarters ----
    __syncthreads();
    if (ctg == 0) {
        #pragma unroll
        for (int i = 0; i < 2; i++)
            #pragma unroll
            for (int h2 = 0; h2 < 2; h2++) {
                const int row = wm * 32 + i * 16 + h2 * 8 + g;
                stats[row * 4 + wn] = l_[i * 2 + h2];
            }
    }
    __syncthreads();
    float inv[4];
    #pragma unroll
    for (int i = 0; i < 2; i++)
        #pragma unroll
        for (int h2 = 0; h2 < 2; h2++) {
            const int row = wm * 32 + i * 16 + h2 * 8 + g;
            inv[i * 2 + h2] = 1.f / (stats[row * 4 + 0] + stats[row * 4 + 1]
                                   + stats[row * 4 + 2] + stats[row * 4 + 3]);
        }

    float o[2][2][4];
    #pragma unroll
    for (int i = 0; i < 2; i++)
        #pragma unroll
        for (int j = 0; j < 2; j++)
            #pragma unroll
            for (int r = 0; r < 4; r++) o[i][j][r] = 0.f;

    auto issueV = [&](int kt) {
        #pragma unroll
        for (int u = 0; u < 2; u++)
            cpa(bVh + cd[u], Vgh + (size_t)(kt * 128 + cr[u]) * DK + cs[u] * 8);
        cpc();
    };

    issueK(0, 0);

    // ============================ pass B ============================
    for (int kt = 0; kt < 16; kt++) {
        CPW(0);
        __syncthreads();
        issueV(kt);
        if (kt < 15) issueK(kt + 1, (kt + 1) & 1);

        const u32 bKh = sb + 36864u + (u32)(kt & 1) * 18432u;

        float s[2][4][4];
        #pragma unroll
        for (int i = 0; i < 2; i++)
            #pragma unroll
            for (int j = 0; j < 4; j++)
                #pragma unroll
                for (int r = 0; r < 4; r++) s[i][j][r] = 0.f;

        #pragma unroll
        for (int ch = 0; ch < 4; ch++) {
            u32 a[2][2][4];
            #pragma unroll
            for (int i = 0; i < 2; i++) {
                const u32 ad = (u32)(wm * 32 + i * 16) * 144 + ch * 32 + lro36;
                ldsm4(a[i][0], bQh + ad);
                ldsm4(a[i][1], bQl + ad);
            }
            #pragma unroll
            for (int jp = 0; jp < 2; jp++) {
                u32 bfh[4];
                ldsm4(bfh, bKh + (u32)(wn * 32 + jp * 16) * 144 + ch * 32 + lro36);
                #pragma unroll
                for (int jj = 0; jj < 2; jj++) {
                    const int j = jp * 2 + jj;
                    const u32 b0h = bfh[jj], b1h = bfh[2 + jj];
                    #pragma unroll
                    for (int i = 0; i < 2; i++) {
                        mma16816(s[i][j], a[i][0][0], a[i][0][1], a[i][0][2], a[i][0][3], b0h, b1h);
                        mma16816(s[i][j], a[i][1][0], a[i][1][1], a[i][1][2], a[i][1][3], b0h, b1h);
                    }
                }
            }
        }

        // normalized weights -> gmem + single-fp16 W into smem
        #pragma unroll
        for (int i = 0; i < 2; i++)
            #pragma unroll
            for (int h2 = 0; h2 < 2; h2++) {
                const int idx = i * 2 + h2;
                const int row = wm * 32 + i * 16 + h2 * 8 + g;
                #pragma unroll
                for (int j = 0; j < 4; j++) {
                    const float w0 = ex2(s[i][j][h2*2])   * inv[idx];
                    const float w1 = ex2(s[i][j][h2*2+1]) * inv[idx];
                    if (wout)
                        *(float2*)(wout + ((size_t)bh * TT + q0 + row) * TT
                                        + kt * 128 + wn * 32 + j * 8 + ctg * 2)
                            = make_float2(w0, w1);
                    __half2 wh2 = __floats2half2_rn(w0, w1);
                    sWh[row * 68 + wn * 16 + j * 4 + ctg] = *(u32*)&wh2;
                }
            }

        if (kt < 15) { CPW(1); } else { CPW(0); }
        __syncthreads();

        // AV: O += W @ V   (single term: W x Vh)
        #pragma unroll
        for (int ch = 0; ch < 8; ch++) {
            u32 aw[2][4];
            #pragma unroll
            for (int i = 0; i < 2; i++)
                ldsm4(aw[i], bWh + (u32)(wm * 32 + i * 16) * 272 + ch * 32 + lro68);
            u32 bvh[4];
            const u32 vd = (u32)(ch * 16) * 144 + (u32)(wn * 16) * 2 + lro36;
            ldsm4t(bvh, bVh + vd);
            #pragma unroll
            for (int j = 0; j < 2; j++) {
                #pragma unroll
                for (int i = 0; i < 2; i++)
                    mma16816(o[i][j], aw[i][0], aw[i][1], aw[i][2], aw[i][3],
                             bvh[j * 2], bvh[j * 2 + 1]);
            }
        }
    }

    // epilogue: split O -> attn scratch [B,T,D]
    __half* Oh = g_sh + 7 * SEG;
    __half* Ol = g_sl + 7 * SEG;
    #pragma unroll
    for (int i = 0; i < 2; i++)
        #pragma unroll
        for (int h2 = 0; h2 < 2; h2++) {
            const int row = q0 + wm * 32 + i * 16 + h2 * 8 + g;
            #pragma unroll
            for (int j = 0; j < 2; j++) {
                const int col = head * 64 + wn * 16 + j * 8 + ctg * 2;
                u32 hi, lo;
                split2(o[i][j][h2*2], o[i][j][h2*2+1], hi, lo);
                const size_t e = ((size_t)bb * TT + row) * DD + col;
                *(u32*)(Oh + e) = hi;
                *(u32*)(Ol + e) = lo;
            }
        }
}

// ---------------------------------------------------------------------------
extern "C" void kernel_launch(void* const* d_in, const int* in_sizes, int n_in,
                              void* d_out, int out_size)
{
    const float* query = (const float*)d_in[0];
    const float* key_  = (const float*)d_in[1];
    const float* value = (const float*)d_in[2];
    const float* W_q   = (const float*)d_in[3];
    const float* W_k   = (const float*)d_in[4];
    const float* W_v   = (const float*)d_in[5];
    const float* W_o   = (const float*)d_in[6];

    split_inputs<<<dim3(1024, 7), 256>>>(query, key_, value, W_q, W_k, W_v, W_o);

    const int psmem = 61440;
    cudaFuncSetAttribute(proj_mma,
                         cudaFuncAttributeMaxDynamicSharedMemorySize, psmem);
    proj_mma<<<dim3(8, 32, 3), 512, psmem>>>(nullptr, 1);   // Q, K, V

    const size_t OUT_E = (size_t)BB * TT * DD;
    const size_t W_E   = (size_t)BB * HH * TT * (size_t)TT;
    float* wout = nullptr;
    if ((size_t)out_size >= OUT_E + W_E)
        wout = (float*)d_out + OUT_E;

    const int asmem = 126976;
    cudaFuncSetAttribute(attn_mma,
                         cudaFuncAttributeMaxDynamicSharedMemorySize, asmem);
    attn_mma<<<dim3(TT / 128, BB * HH), 512, asmem>>>(wout);

    proj_mma<<<dim3(8, 32, 1), 512, psmem>>>((float*)d_out, 0);   // O projection
}